// round 14
// baseline (speedup 1.0000x reference)
#include <cuda_runtime.h>
#include <cuda_bf16.h>
#include <cuda_fp16.h>
#include <cstdint>

#define N_NODES 100000
#define N_EDGES 800000
#define H 128
#define HE 256
#define EPS 1e-5f

// ---------------- shared geometry ----------------
#define M_TILE 128
#define N_TILES (N_EDGES / M_TILE)
#define SA_STRIDE 264       // padded elems per A row (528B ≡ 16 mod 128)
#define SB_STRIDE 136       // padded elems per B row (272B ≡ 16 mod 128)
#define ECHUNK 17408        // 64 rows * 136 * 2B (fp16)

// ---------------- edge kernel smem (persistent, all B resident) ----------------
#define OFF_AHI  1536
#define OFF_SB   (1536 + 67584)             // 69120
#define EDGE_SMEM (69120 + 8 * ECHUNK)      // 208384 (1 CTA/SM)

// ---------------- node kernel smem ----------------
#define OFF_A1HI  4608
#define OFF_A1LO  (4608 + 34816)
#define OFF_NB    (4608 + 69632)            // 74240
#define NODE_SMEM (OFF_NB + 2 * ECHUNK)     // 109056

// ---------------- globals ----------------
__device__ float g_dh[(size_t)N_NODES * H];
__device__ int g_idx_is64;
__device__ __align__(1024) unsigned char g_Bh16[8 * ECHUNK];     // edge weights fp16
__device__ __align__(1024) unsigned char g_Bn16[16 * ECHUNK];    // node weights fp16

// ===========================================================================
// PTX helpers (baseline ISA only)
// ===========================================================================
__device__ __forceinline__ uint32_t smem_u32(const void* p) {
    uint32_t a;
    asm("{ .reg .u64 t; cvta.to.shared.u64 t, %1; cvt.u32.u64 %0, t; }" : "=r"(a) : "l"(p));
    return a;
}
__device__ __forceinline__ void ldsm_x4(uint32_t* r, uint32_t addr) {
    asm volatile("ldmatrix.sync.aligned.m8n8.x4.shared.b16 {%0,%1,%2,%3}, [%4];"
                 : "=r"(r[0]), "=r"(r[1]), "=r"(r[2]), "=r"(r[3]) : "r"(addr));
}
__device__ __forceinline__ void ldsm_x4_t(uint32_t* r, uint32_t addr) {
    asm volatile("ldmatrix.sync.aligned.m8n8.x4.trans.shared.b16 {%0,%1,%2,%3}, [%4];"
                 : "=r"(r[0]), "=r"(r[1]), "=r"(r[2]), "=r"(r[3]) : "r"(addr));
}
// fp32-accumulate fp16 mma (node kernel)
__device__ __forceinline__ void mma16816h(float* d, const uint32_t* a, uint32_t b0, uint32_t b1) {
    asm volatile("mma.sync.aligned.m16n8k16.row.col.f32.f16.f16.f32 "
                 "{%0,%1,%2,%3}, {%4,%5,%6,%7}, {%8,%9}, {%0,%1,%2,%3};"
                 : "+f"(d[0]), "+f"(d[1]), "+f"(d[2]), "+f"(d[3])
                 : "r"(a[0]), "r"(a[1]), "r"(a[2]), "r"(a[3]), "r"(b0), "r"(b1));
}
// fp16-accumulate fp16 mma (edge kernel)
__device__ __forceinline__ void mma16816hh(uint32_t* d, const uint32_t* a, uint32_t b0, uint32_t b1) {
    asm volatile("mma.sync.aligned.m16n8k16.row.col.f16.f16.f16.f16 "
                 "{%0,%1}, {%2,%3,%4,%5}, {%6,%7}, {%0,%1};"
                 : "+r"(d[0]), "+r"(d[1])
                 : "r"(a[0]), "r"(a[1]), "r"(a[2]), "r"(a[3]), "r"(b0), "r"(b1));
}
__device__ __forceinline__ void cp_async16(uint32_t saddr, const void* g) {
    asm volatile("cp.async.cg.shared.global [%0], [%1], 16;" :: "r"(saddr), "l"(g));
}
#define CP_COMMIT() asm volatile("cp.async.commit_group;")
#define CP_WAIT0()  asm volatile("cp.async.wait_group 0;" ::: "memory")

__device__ __forceinline__ uint32_t pack_h(float v0, float v1) {
    return (uint32_t)__half_as_ushort(__float2half_rn(v0)) |
           ((uint32_t)__half_as_ushort(__float2half_rn(v1)) << 16);
}
__device__ __forceinline__ void split_pack_h(float v0, float v1, uint32_t& hi, uint32_t& lo) {
    __half h0 = __float2half_rn(v0), h1 = __float2half_rn(v1);
    hi = (uint32_t)__half_as_ushort(h0) | ((uint32_t)__half_as_ushort(h1) << 16);
    float r0 = v0 - __half2float(h0), r1 = v1 - __half2float(h1);
    lo = (uint32_t)__half_as_ushort(__float2half_rn(r0)) |
         ((uint32_t)__half_as_ushort(__float2half_rn(r1)) << 16);
}
__device__ __forceinline__ float2 unpack_h2sum(uint32_t hi, uint32_t lo) {
    float2 r;
    r.x = __half2float(__ushort_as_half((unsigned short)(hi & 0xffff))) +
          __half2float(__ushort_as_half((unsigned short)(lo & 0xffff)));
    r.y = __half2float(__ushort_as_half((unsigned short)(hi >> 16))) +
          __half2float(__ushort_as_half((unsigned short)(lo >> 16)));
    return r;
}

// edge k16 step: fp16-acc, single-term, 16 mma
#define KSTEP_E1H(HACC, fAh, sBhi, brow) do { \
    _Pragma("unroll") for (int p = 0; p < 8; p++) { \
        uint32_t bh[4]; \
        uint32_t _bo = b_frag_off + (brow) + (uint32_t)(p * 16) * 2; \
        ldsm_x4_t(bh, (sBhi) + _bo); \
        mma16816hh((HACC)[2 * p],     fAh, bh[0], bh[1]); \
        mma16816hh((HACC)[2 * p + 1], fAh, bh[2], bh[3]); \
    } } while (0)

// node 2-term fp16 k16 step, fp32 acc
#define KSTEP_N2(ACC, fAh, fAl, sBhi, brow) do { \
    _Pragma("unroll") for (int p = 0; p < 8; p++) { \
        uint32_t bh[4]; \
        uint32_t _bo = b_frag_off + (brow) + (uint32_t)(p * 16) * 2; \
        ldsm_x4_t(bh, (sBhi) + _bo); \
        mma16816h((ACC)[2 * p],     fAh, bh[0], bh[1]); \
        mma16816h((ACC)[2 * p],     fAl, bh[0], bh[1]); \
        mma16816h((ACC)[2 * p + 1], fAh, bh[2], bh[3]); \
        mma16816h((ACC)[2 * p + 1], fAl, bh[2], bh[3]); \
    } } while (0)

// ---------------------------------------------------------------------------
__global__ void detect_idx_kernel(const void* eidx) {
    const long long* p = (const long long*)eidx;
    int is64 = 1;
    for (int i = 0; i < 64; i++) {
        long long v = p[i];
        if (v < 0 || v >= N_NODES) { is64 = 0; break; }
    }
    g_idx_is64 = is64;
}

// ---------------------------------------------------------------------------
// Weight prep: all weights -> fp16, padded [K][N] layout
// ---------------------------------------------------------------------------
__global__ void prep_weights_kernel(const float* __restrict__ W1,
                                    const float* __restrict__ W2,
                                    const float* __restrict__ W3,
                                    const float* __restrict__ D1,
                                    const float* __restrict__ D2) {
    int idx = blockIdx.x * 256 + threadIdx.x;    // 0 .. 196607
    if (idx < 65536) {
        int n = idx & 127;
        int krow = idx >> 7;
        const float* W; int k, unit;
        if (krow < 256)      { W = W1; k = krow;       unit = krow >> 6; }
        else if (krow < 384) { W = W2; k = krow - 256; unit = 4 + ((krow - 256) >> 6); }
        else                 { W = W3; k = krow - 384; unit = 6 + ((krow - 384) >> 6); }
        float v = W[(size_t)k * 128 + n];
        int kk = k & 63;
        *(unsigned short*)(g_Bh16 + (size_t)unit * ECHUNK + (size_t)(kk * SB_STRIDE + n) * 2) =
            __half_as_ushort(__float2half_rn(v));
        return;
    }
    float v; int unit, kk, n;
    if (idx < 131072) {
        int i = idx - 65536;                     // D1: 128 x 512
        int k = i >> 9, n512 = i & 511;
        int c = n512 >> 7; n = n512 & 127;
        int half = k >> 6; kk = k & 63;
        unit = 4 * c + half;
        v = D1[(size_t)k * 512 + n512];
    } else {
        int i = idx - 131072;                    // D2: 512 x 128
        int k = i >> 7; n = i & 127;
        int c = k >> 7, krem = k & 127;
        int half = krem >> 6; kk = krem & 63;
        unit = 4 * c + 2 + half;
        v = D2[(size_t)k * 128 + n];
    }
    *(unsigned short*)(g_Bn16 + (size_t)unit * ECHUNK + (size_t)(kk * SB_STRIDE + n) * 2) =
        __half_as_ushort(__float2half_rn(v));
}

// ===========================================================================
// Edge kernel: PERSISTENT CTAs, all 8 B chunks resident, fp16-acc HMMA,
// uninterrupted 3-layer compute per tile, staged atomic scatter
// ===========================================================================
__global__ __launch_bounds__(256, 1)
void edge_mma_kernel(const float* __restrict__ hE, const void* __restrict__ eidx,
                     const float* __restrict__ b1, const float* __restrict__ b2,
                     const float* __restrict__ b3) {
    extern __shared__ char sm[];
    const uint32_t sb = smem_u32(sm);
    const int tid = threadIdx.x, wid = tid >> 5, lane = tid & 31;

    if (tid < 128) {
        ((float*)sm)[tid] = b1[tid];
        ((float*)sm)[128 + tid] = b2[tid];
        ((float*)sm)[256 + tid] = b3[tid];
    }

    // load ALL 8 weight chunks once (139 KB)
    for (int i = tid; i < 8704; i += 256)
        cp_async16(sb + OFF_SB + i * 16, g_Bh16 + i * 16);
    CP_COMMIT();

    const int mrow = lane & 7, mid = lane >> 3;
    const uint32_t a_row_off =
        (uint32_t)((wid * 16 + (mid & 1) * 8 + mrow) * SA_STRIDE + (mid >> 1) * 8) * 2;
    const uint32_t b_frag_off =
        (uint32_t)(((mid & 1) * 8 + mrow) * SB_STRIDE + (mid >> 1) * 8) * 2;
    const int bq = 2 * (lane & 3);
    const int is64 = g_idx_is64;

    uint32_t hacc[16][2];
    uint32_t aH[8][4];
    float* sBias = (float*)sm;
    bool first = true;

#define ZERO_ACC() do { \
    _Pragma("unroll") for (int t = 0; t < 16; t++) { hacc[t][0] = 0u; hacc[t][1] = 0u; } } while (0)

#define COMPUTE_SMEM(c) do { \
    uint32_t _sBhi = sb + OFF_SB + (c) * ECHUNK; \
    _Pragma("unroll") for (int js = 0; js < 4; js++) { \
        uint32_t fAh[4]; \
        uint32_t _acol = (uint32_t)((c) * 64 + js * 16) * 2; \
        ldsm_x4(fAh, sb + OFF_AHI + a_row_off + _acol); \
        KSTEP_E1H(hacc, fAh, _sBhi, (uint32_t)(js * 16 * SB_STRIDE) * 2); \
    } } while (0)

#define COMPUTE_REG(JB, c) do { \
    uint32_t _sBhi = sb + OFF_SB + (c) * ECHUNK; \
    _Pragma("unroll") for (int js = 0; js < 4; js++) { \
        KSTEP_E1H(hacc, aH[(JB) + js], _sBhi, (uint32_t)(js * 16 * SB_STRIDE) * 2); \
    } } while (0)

#define EPILOGUE_RELU(biasBase) do { \
    __half2 _z = __float2half2_rn(0.f); \
    _Pragma("unroll") for (int t = 0; t < 16; t++) { \
        float2 bb = *(float2*)&sBias[(biasBase) + t * 8 + bq]; \
        __half2 hb = __floats2half2_rn(bb.x, bb.y); \
        __half2 v01 = __hmax2(__hadd2(*(__half2*)&hacc[t][0], hb), _z); \
        __half2 v23 = __hmax2(__hadd2(*(__half2*)&hacc[t][1], hb), _z); \
        int _j = t >> 1, _b = (t & 1) * 2; \
        aH[_j][_b]     = *(uint32_t*)&v01; \
        aH[_j][_b + 1] = *(uint32_t*)&v23; \
    } } while (0)

    for (int tile = blockIdx.x; tile < N_TILES; tile += gridDim.x) {
        const long long ebase = (long long)tile * M_TILE;

        // stage layer-1 A: h_E [128 x 256] f32 -> fp16, padded stride
        {
            const float4* gE = (const float4*)(hE + ebase * HE);
            char* aHi = sm + OFF_AHI;
            for (int i = tid; i < 128 * 64; i += 256) {
                float4 v = gE[i];
                int row = i >> 6, c4 = i & 63;
                uint32_t off = (uint32_t)(row * SA_STRIDE + c4 * 4) * 2;
                *(uint2*)(aHi + off) = make_uint2(pack_h(v.x, v.y), pack_h(v.z, v.w));
            }
        }
        if (first) { CP_WAIT0(); first = false; }
        __syncthreads();

        // ---- 3 layers, uninterrupted (B fully resident; L2/L3 A in regs) ----
        ZERO_ACC();
        COMPUTE_SMEM(0); COMPUTE_SMEM(1); COMPUTE_SMEM(2); COMPUTE_SMEM(3);
        EPILOGUE_RELU(0); ZERO_ACC();
        COMPUTE_REG(0, 4); COMPUTE_REG(4, 5);
        EPILOGUE_RELU(128); ZERO_ACC();
        COMPUTE_REG(0, 6); COMPUTE_REG(4, 7);
        __syncthreads();   // all warps done reading A smem before sOut overwrites it

        // ---- layer-3 epilogue: fp16->fp32 + bias -> padded smem -> scatter ----
        {
            float* sOut = (float*)(sm + OFF_AHI);   // reuse A region
            int row0 = wid * 16 + (lane >> 2);
#pragma unroll
            for (int t = 0; t < 16; t++) {
                float2 bb = *(float2*)&sBias[256 + t * 8 + bq];
                __half2 v01 = *(__half2*)&hacc[t][0];
                __half2 v23 = *(__half2*)&hacc[t][1];
                *(float2*)&sOut[row0 * 132 + t * 8 + bq] =
                    make_float2(__low2float(v01) + bb.x, __high2float(v01) + bb.y);
                *(float2*)&sOut[(row0 + 8) * 132 + t * 8 + bq] =
                    make_float2(__low2float(v23) + bb.x, __high2float(v23) + bb.y);
            }
            __syncthreads();

            for (int e = wid; e < 128; e += 8) {
                long long s = is64 ? ((const long long*)eidx)[ebase + e]
                                   : (long long)((const int*)eidx)[ebase + e];
                float* dst = g_dh + (size_t)s * H;
                const float* srow = sOut + e * 132;
#pragma unroll
                for (int q = 0; q < 4; q++) {
                    int col = lane + q * 32;
                    atomicAdd(dst + col, srow[col]);
                }
            }
        }
        __syncthreads();   // scatter reads of sOut done before next tile's A staging
    }
#undef ZERO_ACC
#undef COMPUTE_SMEM
#undef COMPUTE_REG
#undef EPILOGUE_RELU
}

// ===========================================================================
// Node kernel: 2-term fp16-weight HMMA FFN, fp32 acc (unchanged, 211us proven)
// ===========================================================================
__global__ __launch_bounds__(256, 1)
void node_mma_kernel(const float* __restrict__ hV,
                     const float* __restrict__ db1, const float* __restrict__ db2,
                     const float* __restrict__ g1, const float* __restrict__ be1,
                     const float* __restrict__ g2, const float* __restrict__ be2,
                     float* __restrict__ out) {
    extern __shared__ char sm[];
    const uint32_t sb = smem_u32(sm);
    const int tid = threadIdx.x, wid = tid >> 5, lane = tid & 31;
    const long long nbase = (long long)blockIdx.x * 128;

    float* sB = (float*)sm;
    for (int i = tid; i < 512; i += 256) sB[i] = db1[i];
    if (tid < 128) {
        sB[512 + tid] = db2[tid];
        sB[640 + tid] = g1[tid];  sB[768 + tid] = be1[tid];
        sB[896 + tid] = g2[tid];  sB[1024 + tid] = be2[tid];
    }

#define PREFETCH_N(s) do { \
    const unsigned char* _src = g_Bn16 + (s) * ECHUNK; \
    uint32_t _dst = sb + OFF_NB + ((s) & 1) * ECHUNK; \
    for (int i = tid; i < 1088; i += 256) cp_async16(_dst + i * 16, _src + i * 16); \
    CP_COMMIT(); } while (0)

    PREFETCH_N(0);

    const int mrow = lane & 7, mid = lane >> 3;
    const uint32_t a_row_off =
        (uint32_t)((wid * 16 + (mid & 1) * 8 + mrow) * SB_STRIDE + (mid >> 1) * 8) * 2;
    const uint32_t b_frag_off =
        (uint32_t)(((mid & 1) * 8 + mrow) * SB_STRIDE + (mid >> 1) * 8) * 2;
    const int bq = 2 * (lane & 3);
    const int r0 = wid * 16 + (lane >> 2);
    const long long gr0 = nbase + r0, gr1 = gr0 + 8;
    const bool ok0 = gr0 < N_NODES, ok1 = gr1 < N_NODES;

    {
        float x[16][4];
#pragma unroll
        for (int t = 0; t < 16; t++) {
            int col = t * 8 + bq;
            if (ok0) {
                float2 v = *(const float2*)(hV + gr0 * H + col);
                float2 d = *(const float2*)(g_dh + gr0 * H + col);
                x[t][0] = v.x + d.x * (1.f / 30.f);
                x[t][1] = v.y + d.y * (1.f / 30.f);
            } else { x[t][0] = 0.f; x[t][1] = 0.f; }
            if (ok1) {
                float2 v = *(const float2*)(hV + gr1 * H + col);
                float2 d = *(const float2*)(g_dh + gr1 * H + col);
                x[t][2] = v.x + d.x * (1.f / 30.f);
                x[t][3] = v.y + d.y * (1.f / 30.f);
            } else { x[t][2] = 0.f; x[t][3] = 0.f; }
        }
        float s0 = 0.f, s1 = 0.f;
#pragma unroll
        for (int t = 0; t < 16; t++) { s0 += x[t][0] + x[t][1]; s1 += x[t][2] + x[t][3]; }
        s0 += __shfl_xor_sync(~0u, s0, 1); s0 += __shfl_xor_sync(~0u, s0, 2);
        s1 += __shfl_xor_sync(~0u, s1, 1); s1 += __shfl_xor_sync(~0u, s1, 2);
        float m0 = s0 * (1.f / H), m1 = s1 * (1.f / H);
        float q0 = 0.f, q1 = 0.f;
#pragma unroll
        for (int t = 0; t < 16; t++) {
            float d0 = x[t][0] - m0, d1 = x[t][1] - m0;
            float d2 = x[t][2] - m1, d3 = x[t][3] - m1;
            q0 += d0 * d0 + d1 * d1; q1 += d2 * d2 + d3 * d3;
        }
        q0 += __shfl_xor_sync(~0u, q0, 1); q0 += __shfl_xor_sync(~0u, q0, 2);
        q1 += __shfl_xor_sync(~0u, q1, 1); q1 += __shfl_xor_sync(~0u, q1, 2);
        float r0s = rsqrtf(q0 * (1.f / H) + EPS), r1s = rsqrtf(q1 * (1.f / H) + EPS);
#pragma unroll
        for (int t = 0; t < 16; t++) {
            int col = t * 8 + bq;
            float2 gg = *(float2*)&sB[640 + col];
            float2 bb = *(float2*)&sB[768 + col];
            float h0 = (x[t][0] - m0) * r0s * gg.x + bb.x;
            float h1 = (x[t][1] - m0) * r0s * gg.y + bb.y;
            float h2 = (x[t][2] - m1) * r1s * gg.x + bb.x;
            float h3 = (x[t][3] - m1) * r1s * gg.y + bb.y;
            uint32_t hi0, lo0, hi1, lo1;
            split_pack_h(h0, h1, hi0, lo0);
            split_pack_h(h2, h3, hi1, lo1);
            uint32_t o0 = (uint32_t)(r0 * SB_STRIDE + col) * 2;
            uint32_t o1 = (uint32_t)((r0 + 8) * SB_STRIDE + col) * 2;
            *(uint32_t*)(sm + OFF_A1HI + o0) = hi0;
            *(uint32_t*)(sm + OFF_A1LO + o0) = lo0;
            *(uint32_t*)(sm + OFF_A1HI + o1) = hi1;
            *(uint32_t*)(sm + OFF_A1LO + o1) = lo1;
        }
    }
    CP_WAIT0();
    __syncthreads();

    float acc2[16][4];
#pragma unroll
    for (int t = 0; t < 16; t++)
        { acc2[t][0] = 0.f; acc2[t][1] = 0.f; acc2[t][2] = 0.f; acc2[t][3] = 0.f; }

    uint32_t aH[8][4], aL[8][4];

#define NCOMPUTE1(half, s) do { \
    uint32_t _sBhi = sb + OFF_NB + ((s) & 1) * ECHUNK; \
    _Pragma("unroll") for (int js = 0; js < 4; js++) { \
        uint32_t fAh[4], fAl[4]; \
        uint32_t _acol = (uint32_t)((half) * 64 + js * 16) * 2; \
        ldsm_x4(fAh, sb + OFF_A1HI + a_row_off + _acol); \
        ldsm_x4(fAl, sb + OFF_A1LO + a_row_off + _acol); \
        KSTEP_N2(acc1, fAh, fAl, _sBhi, (uint32_t)(js * 16 * SB_STRIDE) * 2); \
    } } while (0)

#define NCOMPUTE2(JB, s) do { \
    uint32_t _sBhi = sb + OFF_NB + ((s) & 1) * ECHUNK; \
    _Pragma("unroll") for (int js = 0; js < 4; js++) { \
        KSTEP_N2(acc2, aH[(JB) + js], aL[(JB) + js], _sBhi, (uint32_t)(js * 16 * SB_STRIDE) * 2); \
    } } while (0)

#pragma unroll 1
    for (int c = 0; c < 4; c++) {
        const int s0u = 4 * c;
        float acc1[16][4];
#pragma unroll
        for (int t = 0; t < 16; t++)
            { acc1[t][0] = 0.f; acc1[t][1] = 0.f; acc1[t][2] = 0.f; acc1[t][3] = 0.f; }

        PREFETCH_N(s0u + 1); NCOMPUTE1(0, s0u);     CP_WAIT0(); __syncthreads();
        PREFETCH_N(s0u + 2); NCOMPUTE1(1, s0u + 1); CP_WAIT0(); __syncthreads();

#pragma unroll
        for (int t = 0; t < 16; t++) {
            float2 bb = *(float2*)&sB[c * 128 + t * 8 + bq];
            float v0 = fmaxf(acc1[t][0] + bb.x, 0.f);
            float v1 = fmaxf(acc1[t][1] + bb.y, 0.f);
            float v2 = fmaxf(acc1[t][2] + bb.x, 0.f);
            float v3 = fmaxf(acc1[t][3] + bb.y, 0.f);
            uint32_t h01, l01, h23, l23;
            split_pack_h(v0, v1, h01, l01);
            split_pack_h(v2, v3, h23, l23);
            int _j = t >> 1, _b = (t & 1) * 2;
            aH[_j][_b] = h01; aH[_j][_b + 1] = h23;
            aL[_j][_b] = l01; aL[_j][_b + 1] = l23;
        }

        PREFETCH_N(s0u + 3); NCOMPUTE2(0, s0u + 2); CP_WAIT0(); __syncthreads();
        if (c < 3) {
            PREFETCH_N(s0u + 4); NCOMPUTE2(4, s0u + 3); CP_WAIT0(); __syncthreads();
        } else {
            NCOMPUTE2(4, s0u + 3); __syncthreads();
        }
    }

    {
        float y[16][4];
#pragma unroll
        for (int t = 0; t < 16; t++) {
            int col = t * 8 + bq;
            float2 d2 = *(float2*)&sB[512 + col];
            uint32_t o0 = (uint32_t)(r0 * SB_STRIDE + col) * 2;
            uint32_t o1 = (uint32_t)((r0 + 8) * SB_STRIDE + col) * 2;
            float2 h01 = unpack_h2sum(*(uint32_t*)(sm + OFF_A1HI + o0),
                                      *(uint32_t*)(sm + OFF_A1LO + o0));
            float2 h23 = unpack_h2sum(*(uint32_t*)(sm + OFF_A1HI + o1),
                                      *(uint32_t*)(sm + OFF_A1LO + o1));
            y[t][0] = h01.x + acc2[t][0] + d2.x;
            y[t][1] = h01.y + acc2[t][1] + d2.y;
            y[t][2] = h23.x + acc2[t][2] + d2.x;
            y[t][3] = h23.y + acc2[t][3] + d2.y;
        }
        float s0 = 0.f, s1 = 0.f;
#pragma unroll
        for (int t = 0; t < 16; t++) { s0 += y[t][0] + y[t][1]; s1 += y[t][2] + y[t][3]; }
        s0 += __shfl_xor_sync(~0u, s0, 1); s0 += __shfl_xor_sync(~0u, s0, 2);
        s1 += __shfl_xor_sync(~0u, s1, 1); s1 += __shfl_xor_sync(~0u, s1, 2);
        float m0 = s0 * (1.f / H), m1 = s1 * (1.f / H);
        float q0 = 0.f, q1 = 0.f;
#pragma unroll
        for (int t = 0; t < 16; t++) {
            float d0 = y[t][0] - m0, d1 = y[t][1] - m0;
            float d2 = y[t][2] - m1, d3 = y[t][3] - m1;
            q0 += d0 * d0 + d1 * d1; q1 += d2 * d2 + d3 * d3;
        }
        q0 += __shfl_xor_sync(~0u, q0, 1); q0 += __shfl_xor_sync(~0u, q0, 2);
        q1 += __shfl_xor_sync(~0u, q1, 1); q1 += __shfl_xor_sync(~0u, q1, 2);
        float r0s = rsqrtf(q0 * (1.f / H) + EPS), r1s = rsqrtf(q1 * (1.f / H) + EPS);
#pragma unroll
        for (int t = 0; t < 16; t++) {
            int col = t * 8 + bq;
            float2 gg = *(float2*)&sB[896 + col];
            float2 bb = *(float2*)&sB[1024 + col];
            if (ok0) {
                float2 o;
                o.x = (y[t][0] - m0) * r0s * gg.x + bb.x;
                o.y = (y[t][1] - m0) * r0s * gg.y + bb.y;
                *(float2*)(out + gr0 * H + col) = o;
            }
            if (ok1) {
                float2 o;
                o.x = (y[t][2] - m1) * r1s * gg.x + bb.x;
                o.y = (y[t][3] - m1) * r1s * gg.y + bb.y;
                *(float2*)(out + gr1 * H + col) = o;
            }
        }
    }
#undef PREFETCH_N
#undef NCOMPUTE1
#undef NCOMPUTE2
}

// ===========================================================================
extern "C" void kernel_launch(void* const* d_in, const int* in_sizes, int n_in,
                              void* d_out, int out_size) {
    const float* h_V  = (const float*)d_in[0];
    const float* h_E  = (const float*)d_in[1];
    const void*  eidx = (const void*)d_in[2];
    const float* W1 = (const float*)d_in[3];
    const float* b1 = (const float*)d_in[4];
    const float* W2 = (const float*)d_in[5];
    const float* b2 = (const float*)d_in[6];
    const float* W3 = (const float*)d_in[7];
    const float* b3 = (const float*)d_in[8];
    const float* D1 = (const float*)d_in[9];
    const float* db1 = (const float*)d_in[10];
    const float* D2 = (const float*)d_in[11];
    const float* db2 = (const float*)d_in[12];
    const float* g1 = (const float*)d_in[13];
    const float* be1 = (const float*)d_in[14];
    const float* g2 = (const float*)d_in[15];
    const float* be2 = (const float*)d_in[16];
    float* out = (float*)d_out;

    cudaFuncSetAttribute(edge_mma_kernel, cudaFuncAttributeMaxDynamicSharedMemorySize, EDGE_SMEM);
    cudaFuncSetAttribute(node_mma_kernel, cudaFuncAttributeMaxDynamicSharedMemorySize, NODE_SMEM);

    void* dh_ptr = nullptr;
    cudaGetSymbolAddress(&dh_ptr, g_dh);
    cudaMemsetAsync(dh_ptr, 0, sizeof(float) * (size_t)N_NODES * H, 0);

    detect_idx_kernel<<<1, 1>>>(eidx);
    prep_weights_kernel<<<768, 256>>>(W1, W2, W3, D1, D2);
    edge_mma_kernel<<<148, 256, EDGE_SMEM>>>(h_E, eidx, b1, b2, b3);
    node_mma_kernel<<<(N_NODES + 127) / 128, 256, NODE_SMEM>>>(
        h_V, db1, db2, g1, be1, g2, be2, out);
}

// round 15
// speedup vs baseline: 1.3682x; 1.3682x over previous
#include <cuda_runtime.h>
#include <cuda_bf16.h>
#include <cuda_fp16.h>
#include <cstdint>

#define N_NODES 100000
#define N_EDGES 800000
#define H 128
#define HE 256
#define EPS 1e-5f

// ---------------- shared geometry ----------------
#define M_TILE 128
#define SA_STRIDE 264       // padded elems per A row (528B ≡ 16 mod 128)
#define SB_STRIDE 136       // padded elems per B row (272B ≡ 16 mod 128)
#define ECHUNK 17408        // 64 rows * 136 * 2B (fp16)

// ---------------- edge kernel smem (R13 config) ----------------
#define OFF_AHI  1536
#define OFF_SB   (1536 + 67584)             // 69120
#define EDGE_SMEM (69120 + 2 * ECHUNK)      // 103936 -> 2 CTAs/SM

// ---------------- node kernel smem ----------------
#define OFF_A1HI 4608
#define OFF_A1LO (4608 + 34816)             // 39424
#define OFF_A2   (4608 + 69632)             // 74240  (GEMM2 A operand)
#define OFF_NB   (74240 + 34816)            // 109056
#define NODE_SMEM (OFF_NB + 2 * ECHUNK)     // 143872

// ---------------- globals ----------------
__device__ float g_dh[(size_t)N_NODES * H];
__device__ int g_idx_is64;
__device__ __align__(1024) unsigned char g_Bh16[8 * ECHUNK];     // edge weights fp16
__device__ __align__(1024) unsigned char g_Bn16[16 * ECHUNK];    // node weights fp16

// ===========================================================================
// PTX helpers (baseline ISA only)
// ===========================================================================
__device__ __forceinline__ uint32_t smem_u32(const void* p) {
    uint32_t a;
    asm("{ .reg .u64 t; cvta.to.shared.u64 t, %1; cvt.u32.u64 %0, t; }" : "=r"(a) : "l"(p));
    return a;
}
__device__ __forceinline__ void ldsm_x4(uint32_t* r, uint32_t addr) {
    asm volatile("ldmatrix.sync.aligned.m8n8.x4.shared.b16 {%0,%1,%2,%3}, [%4];"
                 : "=r"(r[0]), "=r"(r[1]), "=r"(r[2]), "=r"(r[3]) : "r"(addr));
}
__device__ __forceinline__ void ldsm_x4_t(uint32_t* r, uint32_t addr) {
    asm volatile("ldmatrix.sync.aligned.m8n8.x4.trans.shared.b16 {%0,%1,%2,%3}, [%4];"
                 : "=r"(r[0]), "=r"(r[1]), "=r"(r[2]), "=r"(r[3]) : "r"(addr));
}
// fp32-accumulate fp16 mma (node kernel)
__device__ __forceinline__ void mma16816h(float* d, const uint32_t* a, uint32_t b0, uint32_t b1) {
    asm volatile("mma.sync.aligned.m16n8k16.row.col.f32.f16.f16.f32 "
                 "{%0,%1,%2,%3}, {%4,%5,%6,%7}, {%8,%9}, {%0,%1,%2,%3};"
                 : "+f"(d[0]), "+f"(d[1]), "+f"(d[2]), "+f"(d[3])
                 : "r"(a[0]), "r"(a[1]), "r"(a[2]), "r"(a[3]), "r"(b0), "r"(b1));
}
// fp16-accumulate fp16 mma (edge kernel)
__device__ __forceinline__ void mma16816hh(uint32_t* d, const uint32_t* a, uint32_t b0, uint32_t b1) {
    asm volatile("mma.sync.aligned.m16n8k16.row.col.f16.f16.f16.f16 "
                 "{%0,%1}, {%2,%3,%4,%5}, {%6,%7}, {%0,%1};"
                 : "+r"(d[0]), "+r"(d[1])
                 : "r"(a[0]), "r"(a[1]), "r"(a[2]), "r"(a[3]), "r"(b0), "r"(b1));
}
__device__ __forceinline__ void cp_async16(uint32_t saddr, const void* g) {
    asm volatile("cp.async.cg.shared.global [%0], [%1], 16;" :: "r"(saddr), "l"(g));
}
#define CP_COMMIT() asm volatile("cp.async.commit_group;")
#define CP_WAIT0()  asm volatile("cp.async.wait_group 0;" ::: "memory")

__device__ __forceinline__ uint32_t pack_h(float v0, float v1) {
    return (uint32_t)__half_as_ushort(__float2half_rn(v0)) |
           ((uint32_t)__half_as_ushort(__float2half_rn(v1)) << 16);
}
__device__ __forceinline__ void split_pack_h(float v0, float v1, uint32_t& hi, uint32_t& lo) {
    __half h0 = __float2half_rn(v0), h1 = __float2half_rn(v1);
    hi = (uint32_t)__half_as_ushort(h0) | ((uint32_t)__half_as_ushort(h1) << 16);
    float r0 = v0 - __half2float(h0), r1 = v1 - __half2float(h1);
    lo = (uint32_t)__half_as_ushort(__float2half_rn(r0)) |
         ((uint32_t)__half_as_ushort(__float2half_rn(r1)) << 16);
}
__device__ __forceinline__ float2 unpack_h2sum(uint32_t hi, uint32_t lo) {
    float2 r;
    r.x = __half2float(__ushort_as_half((unsigned short)(hi & 0xffff))) +
          __half2float(__ushort_as_half((unsigned short)(lo & 0xffff)));
    r.y = __half2float(__ushort_as_half((unsigned short)(hi >> 16))) +
          __half2float(__ushort_as_half((unsigned short)(lo >> 16)));
    return r;
}

// edge k16 step: fp16-acc, single-term, 16 mma
#define KSTEP_E1H(HACC, fAh, sBhi, brow) do { \
    _Pragma("unroll") for (int p = 0; p < 8; p++) { \
        uint32_t bh[4]; \
        uint32_t _bo = b_frag_off + (brow) + (uint32_t)(p * 16) * 2; \
        ldsm_x4_t(bh, (sBhi) + _bo); \
        mma16816hh((HACC)[2 * p],     fAh, bh[0], bh[1]); \
        mma16816hh((HACC)[2 * p + 1], fAh, bh[2], bh[3]); \
    } } while (0)

// node single-term fp16 k16 step, fp32 acc, 16 mma
#define KSTEP_N1(ACC, fAh, sBhi, brow) do { \
    _Pragma("unroll") for (int p = 0; p < 8; p++) { \
        uint32_t bh[4]; \
        uint32_t _bo = b_frag_off + (brow) + (uint32_t)(p * 16) * 2; \
        ldsm_x4_t(bh, (sBhi) + _bo); \
        mma16816h((ACC)[2 * p],     fAh, bh[0], bh[1]); \
        mma16816h((ACC)[2 * p + 1], fAh, bh[2], bh[3]); \
    } } while (0)

// ---------------------------------------------------------------------------
__global__ void detect_idx_kernel(const void* eidx) {
    const long long* p = (const long long*)eidx;
    int is64 = 1;
    for (int i = 0; i < 64; i++) {
        long long v = p[i];
        if (v < 0 || v >= N_NODES) { is64 = 0; break; }
    }
    g_idx_is64 = is64;
}

// ---------------------------------------------------------------------------
// Weight prep: all weights -> fp16, padded [K][N] layout
// ---------------------------------------------------------------------------
__global__ void prep_weights_kernel(const float* __restrict__ W1,
                                    const float* __restrict__ W2,
                                    const float* __restrict__ W3,
                                    const float* __restrict__ D1,
                                    const float* __restrict__ D2) {
    int idx = blockIdx.x * 256 + threadIdx.x;    // 0 .. 196607
    if (idx < 65536) {
        int n = idx & 127;
        int krow = idx >> 7;
        const float* W; int k, unit;
        if (krow < 256)      { W = W1; k = krow;       unit = krow >> 6; }
        else if (krow < 384) { W = W2; k = krow - 256; unit = 4 + ((krow - 256) >> 6); }
        else                 { W = W3; k = krow - 384; unit = 6 + ((krow - 384) >> 6); }
        float v = W[(size_t)k * 128 + n];
        int kk = k & 63;
        *(unsigned short*)(g_Bh16 + (size_t)unit * ECHUNK + (size_t)(kk * SB_STRIDE + n) * 2) =
            __half_as_ushort(__float2half_rn(v));
        return;
    }
    float v; int unit, kk, n;
    if (idx < 131072) {
        int i = idx - 65536;                     // D1: 128 x 512
        int k = i >> 9, n512 = i & 511;
        int c = n512 >> 7; n = n512 & 127;
        int half = k >> 6; kk = k & 63;
        unit = 4 * c + half;
        v = D1[(size_t)k * 512 + n512];
    } else {
        int i = idx - 131072;                    // D2: 512 x 128
        int k = i >> 7; n = i & 127;
        int c = k >> 7, krem = k & 127;
        int half = krem >> 6; kk = krem & 63;
        unit = 4 * c + 2 + half;
        v = D2[(size_t)k * 128 + n];
    }
    *(unsigned short*)(g_Bn16 + (size_t)unit * ECHUNK + (size_t)(kk * SB_STRIDE + n) * 2) =
        __half_as_ushort(__float2half_rn(v));
}

// ===========================================================================
// Edge kernel: fp16-acc HMMA 3-layer MLP (exact R13 config, 690.7us proven)
// ===========================================================================
__global__ __launch_bounds__(256, 2)
void edge_mma_kernel(const float* __restrict__ hE, const void* __restrict__ eidx,
                     const float* __restrict__ b1, const float* __restrict__ b2,
                     const float* __restrict__ b3) {
    extern __shared__ char sm[];
    const uint32_t sb = smem_u32(sm);
    const int tid = threadIdx.x, wid = tid >> 5, lane = tid & 31;
    const long long ebase = (long long)blockIdx.x * M_TILE;

    if (tid < 128) {
        ((float*)sm)[tid] = b1[tid];
        ((float*)sm)[128 + tid] = b2[tid];
        ((float*)sm)[256 + tid] = b3[tid];
    }

    for (int i = tid; i < 1088; i += 256)
        cp_async16(sb + OFF_SB + i * 16, g_Bh16 + i * 16);
    CP_COMMIT();

    {
        const float4* gE = (const float4*)(hE + ebase * HE);
        char* aHi = sm + OFF_AHI;
        for (int i = tid; i < 128 * 64; i += 256) {
            int row = i >> 6, c4 = i & 63;
            float4 v = gE[i];
            uint32_t off = (uint32_t)(row * SA_STRIDE + c4 * 4) * 2;
            *(uint2*)(aHi + off) = make_uint2(pack_h(v.x, v.y), pack_h(v.z, v.w));
        }
    }
    CP_WAIT0();
    __syncthreads();

    const int mrow = lane & 7, mid = lane >> 3;
    const uint32_t a_row_off =
        (uint32_t)((wid * 16 + (mid & 1) * 8 + mrow) * SA_STRIDE + (mid >> 1) * 8) * 2;
    const uint32_t b_frag_off =
        (uint32_t)(((mid & 1) * 8 + mrow) * SB_STRIDE + (mid >> 1) * 8) * 2;
    const int bq = 2 * (lane & 3);

    uint32_t hacc[16][2];
    uint32_t aH[8][4];
    float* sBias = (float*)sm;

#define ZERO_ACC() do { \
    _Pragma("unroll") for (int t = 0; t < 16; t++) { hacc[t][0] = 0u; hacc[t][1] = 0u; } } while (0)

#define PREFETCH(c) do { \
    const unsigned char* _src = g_Bh16 + (c) * ECHUNK; \
    uint32_t _dst = sb + OFF_SB + ((c) & 1) * ECHUNK; \
    for (int i = tid; i < 1088; i += 256) cp_async16(_dst + i * 16, _src + i * 16); \
    CP_COMMIT(); } while (0)

#define COMPUTE_SMEM(c) do { \
    uint32_t _sBhi = sb + OFF_SB + ((c) & 1) * ECHUNK; \
    _Pragma("unroll") for (int js = 0; js < 4; js++) { \
        uint32_t fAh[4]; \
        uint32_t _acol = (uint32_t)((c) * 64 + js * 16) * 2; \
        ldsm_x4(fAh, sb + OFF_AHI + a_row_off + _acol); \
        KSTEP_E1H(hacc, fAh, _sBhi, (uint32_t)(js * 16 * SB_STRIDE) * 2); \
    } } while (0)

#define COMPUTE_REG(JB, c) do { \
    uint32_t _sBhi = sb + OFF_SB + ((c) & 1) * ECHUNK; \
    _Pragma("unroll") for (int js = 0; js < 4; js++) { \
        KSTEP_E1H(hacc, aH[(JB) + js], _sBhi, (uint32_t)(js * 16 * SB_STRIDE) * 2); \
    } } while (0)

#define EPILOGUE_RELU(biasBase) do { \
    __half2 _z = __float2half2_rn(0.f); \
    _Pragma("unroll") for (int t = 0; t < 16; t++) { \
        float2 bb = *(float2*)&sBias[(biasBase) + t * 8 + bq]; \
        __half2 hb = __floats2half2_rn(bb.x, bb.y); \
        __half2 v01 = __hmax2(__hadd2(*(__half2*)&hacc[t][0], hb), _z); \
        __half2 v23 = __hmax2(__hadd2(*(__half2*)&hacc[t][1], hb), _z); \
        int _j = t >> 1, _b = (t & 1) * 2; \
        aH[_j][_b]     = *(uint32_t*)&v01; \
        aH[_j][_b + 1] = *(uint32_t*)&v23; \
    } } while (0)

    ZERO_ACC();
    PREFETCH(1); COMPUTE_SMEM(0); CP_WAIT0(); __syncthreads();
    PREFETCH(2); COMPUTE_SMEM(1); CP_WAIT0(); __syncthreads();
    PREFETCH(3); COMPUTE_SMEM(2); CP_WAIT0(); __syncthreads();
    PREFETCH(4); COMPUTE_SMEM(3); CP_WAIT0(); __syncthreads();
    EPILOGUE_RELU(0); ZERO_ACC();
    PREFETCH(5); COMPUTE_REG(0, 4); CP_WAIT0(); __syncthreads();
    PREFETCH(6); COMPUTE_REG(4, 5); CP_WAIT0(); __syncthreads();
    EPILOGUE_RELU(128); ZERO_ACC();
    PREFETCH(7); COMPUTE_REG(0, 6); CP_WAIT0(); __syncthreads();
    COMPUTE_REG(4, 7); __syncthreads();

    {
        float* sOut = (float*)(sm + OFF_AHI);
        int row0 = wid * 16 + (lane >> 2);
#pragma unroll
        for (int t = 0; t < 16; t++) {
            float2 bb = *(float2*)&sBias[256 + t * 8 + bq];
            __half2 v01 = *(__half2*)&hacc[t][0];
            __half2 v23 = *(__half2*)&hacc[t][1];
            *(float2*)&sOut[row0 * 132 + t * 8 + bq] =
                make_float2(__low2float(v01) + bb.x, __high2float(v01) + bb.y);
            *(float2*)&sOut[(row0 + 8) * 132 + t * 8 + bq] =
                make_float2(__low2float(v23) + bb.x, __high2float(v23) + bb.y);
        }
        __syncthreads();

        const int is64 = g_idx_is64;
        for (int e = wid; e < 128; e += 8) {
            long long s = is64 ? ((const long long*)eidx)[ebase + e]
                               : (long long)((const int*)eidx)[ebase + e];
            float* dst = g_dh + (size_t)s * H;
            const float* srow = sOut + e * 132;
#pragma unroll
            for (int q = 0; q < 4; q++) {
                int col = lane + q * 32;
                atomicAdd(dst + col, srow[col]);
            }
        }
    }
#undef ZERO_ACC
#undef PREFETCH
#undef COMPUTE_SMEM
#undef COMPUTE_REG
#undef EPILOGUE_RELU
}

// ===========================================================================
// Node kernel: SINGLE-TERM fp16 HMMA FFN, fp32 acc; GEMM2 A via smem (A2)
// to keep register pressure low. A1LO kept only for residual reconstruction.
// ===========================================================================
__global__ __launch_bounds__(256, 1)
void node_mma_kernel(const float* __restrict__ hV,
                     const float* __restrict__ db1, const float* __restrict__ db2,
                     const float* __restrict__ g1, const float* __restrict__ be1,
                     const float* __restrict__ g2, const float* __restrict__ be2,
                     float* __restrict__ out) {
    extern __shared__ char sm[];
    const uint32_t sb = smem_u32(sm);
    const int tid = threadIdx.x, wid = tid >> 5, lane = tid & 31;
    const long long nbase = (long long)blockIdx.x * 128;

    float* sB = (float*)sm;
    for (int i = tid; i < 512; i += 256) sB[i] = db1[i];
    if (tid < 128) {
        sB[512 + tid] = db2[tid];
        sB[640 + tid] = g1[tid];  sB[768 + tid] = be1[tid];
        sB[896 + tid] = g2[tid];  sB[1024 + tid] = be2[tid];
    }

#define PREFETCH_N(s) do { \
    const unsigned char* _src = g_Bn16 + (s) * ECHUNK; \
    uint32_t _dst = sb + OFF_NB + ((s) & 1) * ECHUNK; \
    for (int i = tid; i < 1088; i += 256) cp_async16(_dst + i * 16, _src + i * 16); \
    CP_COMMIT(); } while (0)

    PREFETCH_N(0);

    const int mrow = lane & 7, mid = lane >> 3;
    const uint32_t a_row_off =
        (uint32_t)((wid * 16 + (mid & 1) * 8 + mrow) * SB_STRIDE + (mid >> 1) * 8) * 2;
    const uint32_t b_frag_off =
        (uint32_t)(((mid & 1) * 8 + mrow) * SB_STRIDE + (mid >> 1) * 8) * 2;
    const int bq = 2 * (lane & 3);
    const int r0 = wid * 16 + (lane >> 2);
    const long long gr0 = nbase + r0, gr1 = gr0 + 8;
    const bool ok0 = gr0 < N_NODES, ok1 = gr1 < N_NODES;

    // ---- x = hV + dh/30 in fragment layout; LN1 in regs; A1 = fp16 hi(+lo smem) ----
    {
        float x[16][4];
#pragma unroll
        for (int t = 0; t < 16; t++) {
            int col = t * 8 + bq;
            if (ok0) {
                float2 v = *(const float2*)(hV + gr0 * H + col);
                float2 d = *(const float2*)(g_dh + gr0 * H + col);
                x[t][0] = v.x + d.x * (1.f / 30.f);
                x[t][1] = v.y + d.y * (1.f / 30.f);
            } else { x[t][0] = 0.f; x[t][1] = 0.f; }
            if (ok1) {
                float2 v = *(const float2*)(hV + gr1 * H + col);
                float2 d = *(const float2*)(g_dh + gr1 * H + col);
                x[t][2] = v.x + d.x * (1.f / 30.f);
                x[t][3] = v.y + d.y * (1.f / 30.f);
            } else { x[t][2] = 0.f; x[t][3] = 0.f; }
        }
        float s0 = 0.f, s1 = 0.f;
#pragma unroll
        for (int t = 0; t < 16; t++) { s0 += x[t][0] + x[t][1]; s1 += x[t][2] + x[t][3]; }
        s0 += __shfl_xor_sync(~0u, s0, 1); s0 += __shfl_xor_sync(~0u, s0, 2);
        s1 += __shfl_xor_sync(~0u, s1, 1); s1 += __shfl_xor_sync(~0u, s1, 2);
        float m0 = s0 * (1.f / H), m1 = s1 * (1.f / H);
        float q0 = 0.f, q1 = 0.f;
#pragma unroll
        for (int t = 0; t < 16; t++) {
            float d0 = x[t][0] - m0, d1 = x[t][1] - m0;
            float d2 = x[t][2] - m1, d3 = x[t][3] - m1;
            q0 += d0 * d0 + d1 * d1; q1 += d2 * d2 + d3 * d3;
        }
        q0 += __shfl_xor_sync(~0u, q0, 1); q0 += __shfl_xor_sync(~0u, q0, 2);
        q1 += __shfl_xor_sync(~0u, q1, 1); q1 += __shfl_xor_sync(~0u, q1, 2);
        float r0s = rsqrtf(q0 * (1.f / H) + EPS), r1s = rsqrtf(q1 * (1.f / H) + EPS);
#pragma unroll
        for (int t = 0; t < 16; t++) {
            int col = t * 8 + bq;
            float2 gg = *(float2*)&sB[640 + col];
            float2 bb = *(float2*)&sB[768 + col];
            float h0 = (x[t][0] - m0) * r0s * gg.x + bb.x;
            float h1 = (x[t][1] - m0) * r0s * gg.y + bb.y;
            float h2 = (x[t][2] - m1) * r1s * gg.x + bb.x;
            float h3 = (x[t][3] - m1) * r1s * gg.y + bb.y;
            uint32_t hi0, lo0, hi1, lo1;
            split_pack_h(h0, h1, hi0, lo0);
            split_pack_h(h2, h3, hi1, lo1);
            uint32_t o0 = (uint32_t)(r0 * SB_STRIDE + col) * 2;
            uint32_t o1 = (uint32_t)((r0 + 8) * SB_STRIDE + col) * 2;
            *(uint32_t*)(sm + OFF_A1HI + o0) = hi0;
            *(uint32_t*)(sm + OFF_A1LO + o0) = lo0;
            *(uint32_t*)(sm + OFF_A1HI + o1) = hi1;
            *(uint32_t*)(sm + OFF_A1LO + o1) = lo1;
        }
    }
    CP_WAIT0();
    __syncthreads();

    float acc2[16][4];
#pragma unroll
    for (int t = 0; t < 16; t++)
        { acc2[t][0] = 0.f; acc2[t][1] = 0.f; acc2[t][2] = 0.f; acc2[t][3] = 0.f; }

// GEMM1: A from A1HI (single-term)
#define NCOMPUTE1(half, s) do { \
    uint32_t _sBhi = sb + OFF_NB + ((s) & 1) * ECHUNK; \
    _Pragma("unroll") for (int js = 0; js < 4; js++) { \
        uint32_t fAh[4]; \
        uint32_t _acol = (uint32_t)((half) * 64 + js * 16) * 2; \
        ldsm_x4(fAh, sb + OFF_A1HI + a_row_off + _acol); \
        KSTEP_N1(acc1, fAh, _sBhi, (uint32_t)(js * 16 * SB_STRIDE) * 2); \
    } } while (0)

// GEMM2: A from A2 smem (written by this warp; no register fragments held)
#define NCOMPUTE2(half, s) do { \
    uint32_t _sBhi = sb + OFF_NB + ((s) & 1) * ECHUNK; \
    _Pragma("unroll") for (int js = 0; js < 4; js++) { \
        uint32_t fAh[4]; \
        uint32_t _acol = (uint32_t)((half) * 64 + js * 16) * 2; \
        ldsm_x4(fAh, sb + OFF_A2 + a_row_off + _acol); \
        KSTEP_N1(acc2, fAh, _sBhi, (uint32_t)(js * 16 * SB_STRIDE) * 2); \
    } } while (0)

#pragma unroll 1
    for (int c = 0; c < 4; c++) {
        const int s0u = 4 * c;
        float acc1[16][4];
#pragma unroll
        for (int t = 0; t < 16; t++)
            { acc1[t][0] = 0.f; acc1[t][1] = 0.f; acc1[t][2] = 0.f; acc1[t][3] = 0.f; }

        PREFETCH_N(s0u + 1); NCOMPUTE1(0, s0u);     CP_WAIT0(); __syncthreads();
        PREFETCH_N(s0u + 2); NCOMPUTE1(1, s0u + 1); CP_WAIT0(); __syncthreads();

        // bias + relu -> packed fp16 into A2 smem (own rows only)
#pragma unroll
        for (int t = 0; t < 16; t++) {
            float2 bb = *(float2*)&sB[c * 128 + t * 8 + bq];
            float v0 = fmaxf(acc1[t][0] + bb.x, 0.f);
            float v1 = fmaxf(acc1[t][1] + bb.y, 0.f);
            float v2 = fmaxf(acc1[t][2] + bb.x, 0.f);
            float v3 = fmaxf(acc1[t][3] + bb.y, 0.f);
            int col = t * 8 + bq;
            uint32_t o0 = (uint32_t)(r0 * SB_STRIDE + col) * 2;
            uint32_t o1 = (uint32_t)((r0 + 8) * SB_STRIDE + col) * 2;
            *(uint32_t*)(sm + OFF_A2 + o0) = pack_h(v0, v1);
            *(uint32_t*)(sm + OFF_A2 + o1) = pack_h(v2, v3);
        }
        __syncwarp();   // each warp's ldsm reads only rows it wrote

        PREFETCH_N(s0u + 3); NCOMPUTE2(0, s0u + 2); CP_WAIT0(); __syncthreads();
        if (c < 3) {
            PREFETCH_N(s0u + 4); NCOMPUTE2(1, s0u + 3); CP_WAIT0(); __syncthreads();
        } else {
            NCOMPUTE2(1, s0u + 3); __syncthreads();
        }
    }

    // ---- residual + LN2 + store ----
    {
        float y[16][4];
#pragma unroll
        for (int t = 0; t < 16; t++) {
            int col = t * 8 + bq;
            float2 d2 = *(float2*)&sB[512 + col];
            uint32_t o0 = (uint32_t)(r0 * SB_STRIDE + col) * 2;
            uint32_t o1 = (uint32_t)((r0 + 8) * SB_STRIDE + col) * 2;
            float2 h01 = unpack_h2sum(*(uint32_t*)(sm + OFF_A1HI + o0),
                                      *(uint32_t*)(sm + OFF_A1LO + o0));
            float2 h23 = unpack_h2sum(*(uint32_t*)(sm + OFF_A1HI + o1),
                                      *(uint32_t*)(sm + OFF_A1LO + o1));
            y[t][0] = h01.x + acc2[t][0] + d2.x;
            y[t][1] = h01.y + acc2[t][1] + d2.y;
            y[t][2] = h23.x + acc2[t][2] + d2.x;
            y[t][3] = h23.y + acc2[t][3] + d2.y;
        }
        float s0 = 0.f, s1 = 0.f;
#pragma unroll
        for (int t = 0; t < 16; t++) { s0 += y[t][0] + y[t][1]; s1 += y[t][2] + y[t][3]; }
        s0 += __shfl_xor_sync(~0u, s0, 1); s0 += __shfl_xor_sync(~0u, s0, 2);
        s1 += __shfl_xor_sync(~0u, s1, 1); s1 += __shfl_xor_sync(~0u, s1, 2);
        float m0 = s0 * (1.f / H), m1 = s1 * (1.f / H);
        float q0 = 0.f, q1 = 0.f;
#pragma unroll
        for (int t = 0; t < 16; t++) {
            float d0 = y[t][0] - m0, d1 = y[t][1] - m0;
            float d2 = y[t][2] - m1, d3 = y[t][3] - m1;
            q0 += d0 * d0 + d1 * d1; q1 += d2 * d2 + d3 * d3;
        }
        q0 += __shfl_xor_sync(~0u, q0, 1); q0 += __shfl_xor_sync(~0u, q0, 2);
        q1 += __shfl_xor_sync(~0u, q1, 1); q1 += __shfl_xor_sync(~0u, q1, 2);
        float r0s = rsqrtf(q0 * (1.f / H) + EPS), r1s = rsqrtf(q1 * (1.f / H) + EPS);
#pragma unroll
        for (int t = 0; t < 16; t++) {
            int col = t * 8 + bq;
            float2 gg = *(float2*)&sB[896 + col];
            float2 bb = *(float2*)&sB[1024 + col];
            if (ok0) {
                float2 o;
                o.x = (y[t][0] - m0) * r0s * gg.x + bb.x;
                o.y = (y[t][1] - m0) * r0s * gg.y + bb.y;
                *(float2*)(out + gr0 * H + col) = o;
            }
            if (ok1) {
                float2 o;
                o.x = (y[t][2] - m1) * r1s * gg.x + bb.x;
                o.y = (y[t][3] - m1) * r1s * gg.y + bb.y;
                *(float2*)(out + gr1 * H + col) = o;
            }
        }
    }
#undef PREFETCH_N
#undef NCOMPUTE1
#undef NCOMPUTE2
}

// ===========================================================================
extern "C" void kernel_launch(void* const* d_in, const int* in_sizes, int n_in,
                              void* d_out, int out_size) {
    const float* h_V  = (const float*)d_in[0];
    const float* h_E  = (const float*)d_in[1];
    const void*  eidx = (const void*)d_in[2];
    const float* W1 = (const float*)d_in[3];
    const float* b1 = (const float*)d_in[4];
    const float* W2 = (const float*)d_in[5];
    const float* b2 = (const float*)d_in[6];
    const float* W3 = (const float*)d_in[7];
    const float* b3 = (const float*)d_in[8];
    const float* D1 = (const float*)d_in[9];
    const float* db1 = (const float*)d_in[10];
    const float* D2 = (const float*)d_in[11];
    const float* db2 = (const float*)d_in[12];
    const float* g1 = (const float*)d_in[13];
    const float* be1 = (const float*)d_in[14];
    const float* g2 = (const float*)d_in[15];
    const float* be2 = (const float*)d_in[16];
    float* out = (float*)d_out;

    cudaFuncSetAttribute(edge_mma_kernel, cudaFuncAttributeMaxDynamicSharedMemorySize, EDGE_SMEM);
    cudaFuncSetAttribute(node_mma_kernel, cudaFuncAttributeMaxDynamicSharedMemorySize, NODE_SMEM);

    void* dh_ptr = nullptr;
    cudaGetSymbolAddress(&dh_ptr, g_dh);
    cudaMemsetAsync(dh_ptr, 0, sizeof(float) * (size_t)N_NODES * H, 0);

    detect_idx_kernel<<<1, 1>>>(eidx);
    prep_weights_kernel<<<768, 256>>>(W1, W2, W3, D1, D2);
    edge_mma_kernel<<<N_EDGES / M_TILE, 256, EDGE_SMEM>>>(h_E, eidx, b1, b2, b3);
    node_mma_kernel<<<(N_NODES + 127) / 128, 256, NODE_SMEM>>>(
        h_V, db1, db2, g1, be1, g2, be2, out);
}

// round 16
// speedup vs baseline: 1.4225x; 1.0397x over previous
#include <cuda_runtime.h>
#include <cuda_bf16.h>
#include <cuda_fp16.h>
#include <cstdint>

#define N_NODES 100000
#define N_EDGES 800000
#define H 128
#define HE 256
#define EPS 1e-5f

// ---------------- shared geometry ----------------
#define M_TILE 128
#define SA_STRIDE 264       // padded elems per A row (528B ≡ 16 mod 128)
#define SB_STRIDE 136       // padded elems per B row (272B ≡ 16 mod 128)
#define ECHUNK 17408        // 64 rows * 136 * 2B (fp16)
#define HCHUNK 17408        // 64-row A tile bytes (64*136*2)

// ---------------- edge kernel smem (R13/R15 config) ----------------
#define OFF_AHI  1536
#define OFF_SB   (1536 + 67584)             // 69120
#define EDGE_SMEM (69120 + 2 * ECHUNK)      // 103936 -> 2 CTAs/SM

// ---------------- node kernel smem (64 rows, 2 CTAs/SM) ----------------
#define NOFF_A1HI 4608
#define NOFF_A1LO (4608 + HCHUNK)           // 22016
#define NOFF_A2   (22016 + HCHUNK)          // 39424
#define NOFF_NB   (39424 + HCHUNK)          // 56832
#define NODE_SMEM (56832 + 2 * ECHUNK)      // 91648 -> 2 CTAs/SM

// ---------------- globals ----------------
__device__ float g_dh[(size_t)N_NODES * H];
__device__ int g_idx_is64;
__device__ __align__(1024) unsigned char g_Bh16[8 * ECHUNK];     // edge weights fp16
__device__ __align__(1024) unsigned char g_Bn16[16 * ECHUNK];    // node weights fp16

// ===========================================================================
// PTX helpers (baseline ISA only)
// ===========================================================================
__device__ __forceinline__ uint32_t smem_u32(const void* p) {
    uint32_t a;
    asm("{ .reg .u64 t; cvta.to.shared.u64 t, %1; cvt.u32.u64 %0, t; }" : "=r"(a) : "l"(p));
    return a;
}
__device__ __forceinline__ void ldsm_x4(uint32_t* r, uint32_t addr) {
    asm volatile("ldmatrix.sync.aligned.m8n8.x4.shared.b16 {%0,%1,%2,%3}, [%4];"
                 : "=r"(r[0]), "=r"(r[1]), "=r"(r[2]), "=r"(r[3]) : "r"(addr));
}
__device__ __forceinline__ void ldsm_x4_t(uint32_t* r, uint32_t addr) {
    asm volatile("ldmatrix.sync.aligned.m8n8.x4.trans.shared.b16 {%0,%1,%2,%3}, [%4];"
                 : "=r"(r[0]), "=r"(r[1]), "=r"(r[2]), "=r"(r[3]) : "r"(addr));
}
// fp32-accumulate fp16 mma (node kernel)
__device__ __forceinline__ void mma16816h(float* d, const uint32_t* a, uint32_t b0, uint32_t b1) {
    asm volatile("mma.sync.aligned.m16n8k16.row.col.f32.f16.f16.f32 "
                 "{%0,%1,%2,%3}, {%4,%5,%6,%7}, {%8,%9}, {%0,%1,%2,%3};"
                 : "+f"(d[0]), "+f"(d[1]), "+f"(d[2]), "+f"(d[3])
                 : "r"(a[0]), "r"(a[1]), "r"(a[2]), "r"(a[3]), "r"(b0), "r"(b1));
}
// fp16-accumulate fp16 mma (edge kernel)
__device__ __forceinline__ void mma16816hh(uint32_t* d, const uint32_t* a, uint32_t b0, uint32_t b1) {
    asm volatile("mma.sync.aligned.m16n8k16.row.col.f16.f16.f16.f16 "
                 "{%0,%1}, {%2,%3,%4,%5}, {%6,%7}, {%0,%1};"
                 : "+r"(d[0]), "+r"(d[1])
                 : "r"(a[0]), "r"(a[1]), "r"(a[2]), "r"(a[3]), "r"(b0), "r"(b1));
}
__device__ __forceinline__ void cp_async16(uint32_t saddr, const void* g) {
    asm volatile("cp.async.cg.shared.global [%0], [%1], 16;" :: "r"(saddr), "l"(g));
}
#define CP_COMMIT() asm volatile("cp.async.commit_group;")
#define CP_WAIT0()  asm volatile("cp.async.wait_group 0;" ::: "memory")

__device__ __forceinline__ uint32_t pack_h(float v0, float v1) {
    return (uint32_t)__half_as_ushort(__float2half_rn(v0)) |
           ((uint32_t)__half_as_ushort(__float2half_rn(v1)) << 16);
}
__device__ __forceinline__ void split_pack_h(float v0, float v1, uint32_t& hi, uint32_t& lo) {
    __half h0 = __float2half_rn(v0), h1 = __float2half_rn(v1);
    hi = (uint32_t)__half_as_ushort(h0) | ((uint32_t)__half_as_ushort(h1) << 16);
    float r0 = v0 - __half2float(h0), r1 = v1 - __half2float(h1);
    lo = (uint32_t)__half_as_ushort(__float2half_rn(r0)) |
         ((uint32_t)__half_as_ushort(__float2half_rn(r1)) << 16);
}
__device__ __forceinline__ float2 unpack_h2sum(uint32_t hi, uint32_t lo) {
    float2 r;
    r.x = __half2float(__ushort_as_half((unsigned short)(hi & 0xffff))) +
          __half2float(__ushort_as_half((unsigned short)(lo & 0xffff)));
    r.y = __half2float(__ushort_as_half((unsigned short)(hi >> 16))) +
          __half2float(__ushort_as_half((unsigned short)(lo >> 16)));
    return r;
}

// edge k16 step: fp16-acc, single-term, 16 mma
#define KSTEP_E1H(HACC, fAh, sBhi, brow) do { \
    _Pragma("unroll") for (int p = 0; p < 8; p++) { \
        uint32_t bh[4]; \
        uint32_t _bo = b_frag_off + (brow) + (uint32_t)(p * 16) * 2; \
        ldsm_x4_t(bh, (sBhi) + _bo); \
        mma16816hh((HACC)[2 * p],     fAh, bh[0], bh[1]); \
        mma16816hh((HACC)[2 * p + 1], fAh, bh[2], bh[3]); \
    } } while (0)

// node single-term fp16 k16 step, fp32 acc, 16 mma
#define KSTEP_N1(ACC, fAh, sBhi, brow) do { \
    _Pragma("unroll") for (int p = 0; p < 8; p++) { \
        uint32_t bh[4]; \
        uint32_t _bo = b_frag_off + (brow) + (uint32_t)(p * 16) * 2; \
        ldsm_x4_t(bh, (sBhi) + _bo); \
        mma16816h((ACC)[2 * p],     fAh, bh[0], bh[1]); \
        mma16816h((ACC)[2 * p + 1], fAh, bh[2], bh[3]); \
    } } while (0)

// ---------------------------------------------------------------------------
// Weight prep (+ index dtype detection folded in): all weights -> fp16
// ---------------------------------------------------------------------------
__global__ void prep_weights_kernel(const float* __restrict__ W1,
                                    const float* __restrict__ W2,
                                    const float* __restrict__ W3,
                                    const float* __restrict__ D1,
                                    const float* __restrict__ D2,
                                    const void* __restrict__ eidx) {
    int idx = blockIdx.x * 256 + threadIdx.x;    // 0 .. 196607
    if (idx == 0) {
        const long long* p = (const long long*)eidx;
        int is64 = 1;
        for (int i = 0; i < 64; i++) {
            long long v = p[i];
            if (v < 0 || v >= N_NODES) { is64 = 0; break; }
        }
        g_idx_is64 = is64;
    }
    if (idx < 65536) {
        int n = idx & 127;
        int krow = idx >> 7;
        const float* W; int k, unit;
        if (krow < 256)      { W = W1; k = krow;       unit = krow >> 6; }
        else if (krow < 384) { W = W2; k = krow - 256; unit = 4 + ((krow - 256) >> 6); }
        else                 { W = W3; k = krow - 384; unit = 6 + ((krow - 384) >> 6); }
        float v = W[(size_t)k * 128 + n];
        int kk = k & 63;
        *(unsigned short*)(g_Bh16 + (size_t)unit * ECHUNK + (size_t)(kk * SB_STRIDE + n) * 2) =
            __half_as_ushort(__float2half_rn(v));
        return;
    }
    float v; int unit, kk, n;
    if (idx < 131072) {
        int i = idx - 65536;                     // D1: 128 x 512
        int k = i >> 9, n512 = i & 511;
        int c = n512 >> 7; n = n512 & 127;
        int half = k >> 6; kk = k & 63;
        unit = 4 * c + half;
        v = D1[(size_t)k * 512 + n512];
    } else {
        int i = idx - 131072;                    // D2: 512 x 128
        int k = i >> 7; n = i & 127;
        int c = k >> 7, krem = k & 127;
        int half = krem >> 6; kk = krem & 63;
        unit = 4 * c + 2 + half;
        v = D2[(size_t)k * 128 + n];
    }
    *(unsigned short*)(g_Bn16 + (size_t)unit * ECHUNK + (size_t)(kk * SB_STRIDE + n) * 2) =
        __half_as_ushort(__float2half_rn(v));
}

// ===========================================================================
// Edge kernel: fp16-acc HMMA 3-layer MLP (exact R15 config, at MMA floor)
// ===========================================================================
__global__ __launch_bounds__(256, 2)
void edge_mma_kernel(const float* __restrict__ hE, const void* __restrict__ eidx,
                     const float* __restrict__ b1, const float* __restrict__ b2,
                     const float* __restrict__ b3) {
    extern __shared__ char sm[];
    const uint32_t sb = smem_u32(sm);
    const int tid = threadIdx.x, wid = tid >> 5, lane = tid & 31;
    const long long ebase = (long long)blockIdx.x * M_TILE;

    if (tid < 128) {
        ((float*)sm)[tid] = b1[tid];
        ((float*)sm)[128 + tid] = b2[tid];
        ((float*)sm)[256 + tid] = b3[tid];
    }

    for (int i = tid; i < 1088; i += 256)
        cp_async16(sb + OFF_SB + i * 16, g_Bh16 + i * 16);
    CP_COMMIT();

    {
        const float4* gE = (const float4*)(hE + ebase * HE);
        char* aHi = sm + OFF_AHI;
        for (int i = tid; i < 128 * 64; i += 256) {
            int row = i >> 6, c4 = i & 63;
            float4 v = gE[i];
            uint32_t off = (uint32_t)(row * SA_STRIDE + c4 * 4) * 2;
            *(uint2*)(aHi + off) = make_uint2(pack_h(v.x, v.y), pack_h(v.z, v.w));
        }
    }
    CP_WAIT0();
    __syncthreads();

    const int mrow = lane & 7, mid = lane >> 3;
    const uint32_t a_row_off =
        (uint32_t)((wid * 16 + (mid & 1) * 8 + mrow) * SA_STRIDE + (mid >> 1) * 8) * 2;
    const uint32_t b_frag_off =
        (uint32_t)(((mid & 1) * 8 + mrow) * SB_STRIDE + (mid >> 1) * 8) * 2;
    const int bq = 2 * (lane & 3);

    uint32_t hacc[16][2];
    uint32_t aH[8][4];
    float* sBias = (float*)sm;

#define ZERO_ACC() do { \
    _Pragma("unroll") for (int t = 0; t < 16; t++) { hacc[t][0] = 0u; hacc[t][1] = 0u; } } while (0)

#define PREFETCH(c) do { \
    const unsigned char* _src = g_Bh16 + (c) * ECHUNK; \
    uint32_t _dst = sb + OFF_SB + ((c) & 1) * ECHUNK; \
    for (int i = tid; i < 1088; i += 256) cp_async16(_dst + i * 16, _src + i * 16); \
    CP_COMMIT(); } while (0)

#define COMPUTE_SMEM(c) do { \
    uint32_t _sBhi = sb + OFF_SB + ((c) & 1) * ECHUNK; \
    _Pragma("unroll") for (int js = 0; js < 4; js++) { \
        uint32_t fAh[4]; \
        uint32_t _acol = (uint32_t)((c) * 64 + js * 16) * 2; \
        ldsm_x4(fAh, sb + OFF_AHI + a_row_off + _acol); \
        KSTEP_E1H(hacc, fAh, _sBhi, (uint32_t)(js * 16 * SB_STRIDE) * 2); \
    } } while (0)

#define COMPUTE_REG(JB, c) do { \
    uint32_t _sBhi = sb + OFF_SB + ((c) & 1) * ECHUNK; \
    _Pragma("unroll") for (int js = 0; js < 4; js++) { \
        KSTEP_E1H(hacc, aH[(JB) + js], _sBhi, (uint32_t)(js * 16 * SB_STRIDE) * 2); \
    } } while (0)

#define EPILOGUE_RELU(biasBase) do { \
    __half2 _z = __float2half2_rn(0.f); \
    _Pragma("unroll") for (int t = 0; t < 16; t++) { \
        float2 bb = *(float2*)&sBias[(biasBase) + t * 8 + bq]; \
        __half2 hb = __floats2half2_rn(bb.x, bb.y); \
        __half2 v01 = __hmax2(__hadd2(*(__half2*)&hacc[t][0], hb), _z); \
        __half2 v23 = __hmax2(__hadd2(*(__half2*)&hacc[t][1], hb), _z); \
        int _j = t >> 1, _b = (t & 1) * 2; \
        aH[_j][_b]     = *(uint32_t*)&v01; \
        aH[_j][_b + 1] = *(uint32_t*)&v23; \
    } } while (0)

    ZERO_ACC();
    PREFETCH(1); COMPUTE_SMEM(0); CP_WAIT0(); __syncthreads();
    PREFETCH(2); COMPUTE_SMEM(1); CP_WAIT0(); __syncthreads();
    PREFETCH(3); COMPUTE_SMEM(2); CP_WAIT0(); __syncthreads();
    PREFETCH(4); COMPUTE_SMEM(3); CP_WAIT0(); __syncthreads();
    EPILOGUE_RELU(0); ZERO_ACC();
    PREFETCH(5); COMPUTE_REG(0, 4); CP_WAIT0(); __syncthreads();
    PREFETCH(6); COMPUTE_REG(4, 5); CP_WAIT0(); __syncthreads();
    EPILOGUE_RELU(128); ZERO_ACC();
    PREFETCH(7); COMPUTE_REG(0, 6); CP_WAIT0(); __syncthreads();
    COMPUTE_REG(4, 7); __syncthreads();

    {
        float* sOut = (float*)(sm + OFF_AHI);
        int row0 = wid * 16 + (lane >> 2);
#pragma unroll
        for (int t = 0; t < 16; t++) {
            float2 bb = *(float2*)&sBias[256 + t * 8 + bq];
            __half2 v01 = *(__half2*)&hacc[t][0];
            __half2 v23 = *(__half2*)&hacc[t][1];
            *(float2*)&sOut[row0 * 132 + t * 8 + bq] =
                make_float2(__low2float(v01) + bb.x, __high2float(v01) + bb.y);
            *(float2*)&sOut[(row0 + 8) * 132 + t * 8 + bq] =
                make_float2(__low2float(v23) + bb.x, __high2float(v23) + bb.y);
        }
        __syncthreads();

        const int is64 = g_idx_is64;
        for (int e = wid; e < 128; e += 8) {
            long long s = is64 ? ((const long long*)eidx)[ebase + e]
                               : (long long)((const int*)eidx)[ebase + e];
            float* dst = g_dh + (size_t)s * H;
            const float* srow = sOut + e * 132;
#pragma unroll
            for (int q = 0; q < 4; q++) {
                int col = lane + q * 32;
                atomicAdd(dst + col, srow[col]);
            }
        }
    }
#undef ZERO_ACC
#undef PREFETCH
#undef COMPUTE_SMEM
#undef COMPUTE_REG
#undef EPILOGUE_RELU
}

// ===========================================================================
// Node kernel: single-term fp16 HMMA FFN, 64 rows / 128 threads / 2 CTAs/SM
// ===========================================================================
__global__ __launch_bounds__(128, 2)
void node_mma_kernel(const float* __restrict__ hV,
                     const float* __restrict__ db1, const float* __restrict__ db2,
                     const float* __restrict__ g1, const float* __restrict__ be1,
                     const float* __restrict__ g2, const float* __restrict__ be2,
                     float* __restrict__ out) {
    extern __shared__ char sm[];
    const uint32_t sb = smem_u32(sm);
    const int tid = threadIdx.x, wid = tid >> 5, lane = tid & 31;
    const long long nbase = (long long)blockIdx.x * 64;

    float* sB = (float*)sm;
    for (int i = tid; i < 512; i += 128) sB[i] = db1[i];
    if (tid < 128) {
        sB[512 + tid] = db2[tid];
        sB[640 + tid] = g1[tid];  sB[768 + tid] = be1[tid];
        sB[896 + tid] = g2[tid];  sB[1024 + tid] = be2[tid];
    }

#define PREFETCH_N(s) do { \
    const unsigned char* _src = g_Bn16 + (s) * ECHUNK; \
    uint32_t _dst = sb + NOFF_NB + ((s) & 1) * ECHUNK; \
    for (int i = tid; i < 1088; i += 128) cp_async16(_dst + i * 16, _src + i * 16); \
    CP_COMMIT(); } while (0)

    PREFETCH_N(0);

    const int mrow = lane & 7, mid = lane >> 3;
    const uint32_t a_row_off =
        (uint32_t)((wid * 16 + (mid & 1) * 8 + mrow) * SB_STRIDE + (mid >> 1) * 8) * 2;
    const uint32_t b_frag_off =
        (uint32_t)(((mid & 1) * 8 + mrow) * SB_STRIDE + (mid >> 1) * 8) * 2;
    const int bq = 2 * (lane & 3);
    const int r0 = wid * 16 + (lane >> 2);      // 0..63
    const long long gr0 = nbase + r0, gr1 = gr0 + 8;
    const bool ok0 = gr0 < N_NODES, ok1 = gr1 < N_NODES;

    // ---- x = hV + dh/30 in fragment layout; LN1 in regs; A1 = fp16 hi(+lo smem) ----
    {
        float x[16][4];
#pragma unroll
        for (int t = 0; t < 16; t++) {
            int col = t * 8 + bq;
            if (ok0) {
                float2 v = *(const float2*)(hV + gr0 * H + col);
                float2 d = *(const float2*)(g_dh + gr0 * H + col);
                x[t][0] = v.x + d.x * (1.f / 30.f);
                x[t][1] = v.y + d.y * (1.f / 30.f);
            } else { x[t][0] = 0.f; x[t][1] = 0.f; }
            if (ok1) {
                float2 v = *(const float2*)(hV + gr1 * H + col);
                float2 d = *(const float2*)(g_dh + gr1 * H + col);
                x[t][2] = v.x + d.x * (1.f / 30.f);
                x[t][3] = v.y + d.y * (1.f / 30.f);
            } else { x[t][2] = 0.f; x[t][3] = 0.f; }
        }
        float s0 = 0.f, s1 = 0.f;
#pragma unroll
        for (int t = 0; t < 16; t++) { s0 += x[t][0] + x[t][1]; s1 += x[t][2] + x[t][3]; }
        s0 += __shfl_xor_sync(~0u, s0, 1); s0 += __shfl_xor_sync(~0u, s0, 2);
        s1 += __shfl_xor_sync(~0u, s1, 1); s1 += __shfl_xor_sync(~0u, s1, 2);
        float m0 = s0 * (1.f / H), m1 = s1 * (1.f / H);
        float q0 = 0.f, q1 = 0.f;
#pragma unroll
        for (int t = 0; t < 16; t++) {
            float d0 = x[t][0] - m0, d1 = x[t][1] - m0;
            float d2 = x[t][2] - m1, d3 = x[t][3] - m1;
            q0 += d0 * d0 + d1 * d1; q1 += d2 * d2 + d3 * d3;
        }
        q0 += __shfl_xor_sync(~0u, q0, 1); q0 += __shfl_xor_sync(~0u, q0, 2);
        q1 += __shfl_xor_sync(~0u, q1, 1); q1 += __shfl_xor_sync(~0u, q1, 2);
        float r0s = rsqrtf(q0 * (1.f / H) + EPS), r1s = rsqrtf(q1 * (1.f / H) + EPS);
#pragma unroll
        for (int t = 0; t < 16; t++) {
            int col = t * 8 + bq;
            float2 gg = *(float2*)&sB[640 + col];
            float2 bb = *(float2*)&sB[768 + col];
            float h0 = (x[t][0] - m0) * r0s * gg.x + bb.x;
            float h1 = (x[t][1] - m0) * r0s * gg.y + bb.y;
            float h2 = (x[t][2] - m1) * r1s * gg.x + bb.x;
            float h3 = (x[t][3] - m1) * r1s * gg.y + bb.y;
            uint32_t hi0, lo0, hi1, lo1;
            split_pack_h(h0, h1, hi0, lo0);
            split_pack_h(h2, h3, hi1, lo1);
            uint32_t o0 = (uint32_t)(r0 * SB_STRIDE + col) * 2;
            uint32_t o1 = (uint32_t)((r0 + 8) * SB_STRIDE + col) * 2;
            *(uint32_t*)(sm + NOFF_A1HI + o0) = hi0;
            *(uint32_t*)(sm + NOFF_A1LO + o0) = lo0;
            *(uint32_t*)(sm + NOFF_A1HI + o1) = hi1;
            *(uint32_t*)(sm + NOFF_A1LO + o1) = lo1;
        }
    }
    CP_WAIT0();
    __syncthreads();

    float acc2[16][4];
#pragma unroll
    for (int t = 0; t < 16; t++)
        { acc2[t][0] = 0.f; acc2[t][1] = 0.f; acc2[t][2] = 0.f; acc2[t][3] = 0.f; }

#define NCOMPUTE1(half, s) do { \
    uint32_t _sBhi = sb + NOFF_NB + ((s) & 1) * ECHUNK; \
    _Pragma("unroll") for (int js = 0; js < 4; js++) { \
        uint32_t fAh[4]; \
        uint32_t _acol = (uint32_t)((half) * 64 + js * 16) * 2; \
        ldsm_x4(fAh, sb + NOFF_A1HI + a_row_off + _acol); \
        KSTEP_N1(acc1, fAh, _sBhi, (uint32_t)(js * 16 * SB_STRIDE) * 2); \
    } } while (0)

#define NCOMPUTE2(half, s) do { \
    uint32_t _sBhi = sb + NOFF_NB + ((s) & 1) * ECHUNK; \
    _Pragma("unroll") for (int js = 0; js < 4; js++) { \
        uint32_t fAh[4]; \
        uint32_t _acol = (uint32_t)((half) * 64 + js * 16) * 2; \
        ldsm_x4(fAh, sb + NOFF_A2 + a_row_off + _acol); \
        KSTEP_N1(acc2, fAh, _sBhi, (uint32_t)(js * 16 * SB_STRIDE) * 2); \
    } } while (0)

#pragma unroll 1
    for (int c = 0; c < 4; c++) {
        const int s0u = 4 * c;
        float acc1[16][4];
#pragma unroll
        for (int t = 0; t < 16; t++)
            { acc1[t][0] = 0.f; acc1[t][1] = 0.f; acc1[t][2] = 0.f; acc1[t][3] = 0.f; }

        PREFETCH_N(s0u + 1); NCOMPUTE1(0, s0u);     CP_WAIT0(); __syncthreads();
        PREFETCH_N(s0u + 2); NCOMPUTE1(1, s0u + 1); CP_WAIT0(); __syncthreads();

        // bias + relu -> packed fp16 into A2 smem (own rows only)
#pragma unroll
        for (int t = 0; t < 16; t++) {
            float2 bb = *(float2*)&sB[c * 128 + t * 8 + bq];
            float v0 = fmaxf(acc1[t][0] + bb.x, 0.f);
            float v1 = fmaxf(acc1[t][1] + bb.y, 0.f);
            float v2 = fmaxf(acc1[t][2] + bb.x, 0.f);
            float v3 = fmaxf(acc1[t][3] + bb.y, 0.f);
            int col = t * 8 + bq;
            uint32_t o0 = (uint32_t)(r0 * SB_STRIDE + col) * 2;
            uint32_t o1 = (uint32_t)((r0 + 8) * SB_STRIDE + col) * 2;
            *(uint32_t*)(sm + NOFF_A2 + o0) = pack_h(v0, v1);
            *(uint32_t*)(sm + NOFF_A2 + o1) = pack_h(v2, v3);
        }
        __syncwarp();   // each warp's ldsm reads only rows it wrote

        PREFETCH_N(s0u + 3); NCOMPUTE2(0, s0u + 2); CP_WAIT0(); __syncthreads();
        if (c < 3) {
            PREFETCH_N(s0u + 4); NCOMPUTE2(1, s0u + 3); CP_WAIT0(); __syncthreads();
        } else {
            NCOMPUTE2(1, s0u + 3); __syncthreads();
        }
    }

    // ---- residual + LN2 + store ----
    {
        float y[16][4];
#pragma unroll
        for (int t = 0; t < 16; t++) {
            int col = t * 8 + bq;
            float2 d2 = *(float2*)&sB[512 + col];
            uint32_t o0 = (uint32_t)(r0 * SB_STRIDE + col) * 2;
            uint32_t o1 = (uint32_t)((r0 + 8) * SB_STRIDE + col) * 2;
            float2 h01 = unpack_h2sum(*(uint32_t*)(sm + NOFF_A1HI + o0),
                                      *(uint32_t*)(sm + NOFF_A1LO + o0));
            float2 h23 = unpack_h2sum(*(uint32_t*)(sm + NOFF_A1HI + o1),
                                      *(uint32_t*)(sm + NOFF_A1LO + o1));
            y[t][0] = h01.x + acc2[t][0] + d2.x;
            y[t][1] = h01.y + acc2[t][1] + d2.y;
            y[t][2] = h23.x + acc2[t][2] + d2.x;
            y[t][3] = h23.y + acc2[t][3] + d2.y;
        }
        float s0 = 0.f, s1 = 0.f;
#pragma unroll
        for (int t = 0; t < 16; t++) { s0 += y[t][0] + y[t][1]; s1 += y[t][2] + y[t][3]; }
        s0 += __shfl_xor_sync(~0u, s0, 1); s0 += __shfl_xor_sync(~0u, s0, 2);
        s1 += __shfl_xor_sync(~0u, s1, 1); s1 += __shfl_xor_sync(~0u, s1, 2);
        float m0 = s0 * (1.f / H), m1 = s1 * (1.f / H);
        float q0 = 0.f, q1 = 0.f;
#pragma unroll
        for (int t = 0; t < 16; t++) {
            float d0 = y[t][0] - m0, d1 = y[t][1] - m0;
            float d2 = y[t][2] - m1, d3 = y[t][3] - m1;
            q0 += d0 * d0 + d1 * d1; q1 += d2 * d2 + d3 * d3;
        }
        q0 += __shfl_xor_sync(~0u, q0, 1); q0 += __shfl_xor_sync(~0u, q0, 2);
        q1 += __shfl_xor_sync(~0u, q1, 1); q1 += __shfl_xor_sync(~0u, q1, 2);
        float r0s = rsqrtf(q0 * (1.f / H) + EPS), r1s = rsqrtf(q1 * (1.f / H) + EPS);
#pragma unroll
        for (int t = 0; t < 16; t++) {
            int col = t * 8 + bq;
            float2 gg = *(float2*)&sB[896 + col];
            float2 bb = *(float2*)&sB[1024 + col];
            if (ok0) {
                float2 o;
                o.x = (y[t][0] - m0) * r0s * gg.x + bb.x;
                o.y = (y[t][1] - m0) * r0s * gg.y + bb.y;
                *(float2*)(out + gr0 * H + col) = o;
            }
            if (ok1) {
                float2 o;
                o.x = (y[t][2] - m1) * r1s * gg.x + bb.x;
                o.y = (y[t][3] - m1) * r1s * gg.y + bb.y;
                *(float2*)(out + gr1 * H + col) = o;
            }
        }
    }
#undef PREFETCH_N
#undef NCOMPUTE1
#undef NCOMPUTE2
}

// ===========================================================================
extern "C" void kernel_launch(void* const* d_in, const int* in_sizes, int n_in,
                              void* d_out, int out_size) {
    const float* h_V  = (const float*)d_in[0];
    const float* h_E  = (const float*)d_in[1];
    const void*  eidx = (const void*)d_in[2];
    const float* W1 = (const float*)d_in[3];
    const float* b1 = (const float*)d_in[4];
    const float* W2 = (const float*)d_in[5];
    const float* b2 = (const float*)d_in[6];
    const float* W3 = (const float*)d_in[7];
    const float* b3 = (const float*)d_in[8];
    const float* D1 = (const float*)d_in[9];
    const float* db1 = (const float*)d_in[10];
    const float* D2 = (const float*)d_in[11];
    const float* db2 = (const float*)d_in[12];
    const float* g1 = (const float*)d_in[13];
    const float* be1 = (const float*)d_in[14];
    const float* g2 = (const float*)d_in[15];
    const float* be2 = (const float*)d_in[16];
    float* out = (float*)d_out;

    cudaFuncSetAttribute(edge_mma_kernel, cudaFuncAttributeMaxDynamicSharedMemorySize, EDGE_SMEM);
    cudaFuncSetAttribute(node_mma_kernel, cudaFuncAttributeMaxDynamicSharedMemorySize, NODE_SMEM);

    void* dh_ptr = nullptr;
    cudaGetSymbolAddress(&dh_ptr, g_dh);
    cudaMemsetAsync(dh_ptr, 0, sizeof(float) * (size_t)N_NODES * H, 0);

    prep_weights_kernel<<<768, 256>>>(W1, W2, W3, D1, D2, eidx);
    edge_mma_kernel<<<N_EDGES / M_TILE, 256, EDGE_SMEM>>>(h_E, eidx, b1, b2, b3);
    node_mma_kernel<<<(N_NODES + 63) / 64, 128, NODE_SMEM>>>(
        h_V, db1, db2, g1, be1, g2, be2, out);
}

// round 17
// speedup vs baseline: 1.5103x; 1.0617x over previous
#include <cuda_runtime.h>
#include <cuda_bf16.h>
#include <cuda_fp16.h>
#include <cstdint>

#define N_NODES 100000
#define N_EDGES 800000
#define H 128
#define HE 256
#define EPS 1e-5f

// ---------------- shared geometry ----------------
#define M_TILE 128
#define SA_STRIDE 264       // padded elems per A row (528B ≡ 16 mod 128)
#define SB_STRIDE 136       // padded elems per B row (272B ≡ 16 mod 128)
#define ECHUNK 17408        // 64 rows * 136 * 2B (fp16)
#define HCHUNK 17408        // 64-row A tile bytes (64*136*2)

// ---------------- edge kernel smem ----------------
#define OFF_AHI  1536
#define OFF_SB   (1536 + 67584)             // 69120
#define EDGE_SMEM (69120 + 2 * ECHUNK)      // 103936 -> 2 CTAs/SM

// ---------------- node kernel smem (64 rows, 2 CTAs/SM) ----------------
#define NOFF_A1HI 4608
#define NOFF_A1LO (4608 + HCHUNK)           // 22016
#define NOFF_A2   (22016 + HCHUNK)          // 39424
#define NOFF_NB   (39424 + HCHUNK)          // 56832
#define NODE_SMEM (56832 + 2 * ECHUNK)      // 91648 -> 2 CTAs/SM

// ---------------- globals ----------------
__device__ float g_dh[(size_t)N_NODES * H];
__device__ int g_idx_is64;
__device__ __align__(1024) unsigned char g_Bh16[8 * ECHUNK];     // edge weights fp16
__device__ __align__(1024) unsigned char g_Bn16[16 * ECHUNK];    // node weights fp16

// ===========================================================================
// PTX helpers (baseline ISA only)
// ===========================================================================
__device__ __forceinline__ uint32_t smem_u32(const void* p) {
    uint32_t a;
    asm("{ .reg .u64 t; cvta.to.shared.u64 t, %1; cvt.u32.u64 %0, t; }" : "=r"(a) : "l"(p));
    return a;
}
__device__ __forceinline__ void ldsm_x4(uint32_t* r, uint32_t addr) {
    asm volatile("ldmatrix.sync.aligned.m8n8.x4.shared.b16 {%0,%1,%2,%3}, [%4];"
                 : "=r"(r[0]), "=r"(r[1]), "=r"(r[2]), "=r"(r[3]) : "r"(addr));
}
__device__ __forceinline__ void ldsm_x4_t(uint32_t* r, uint32_t addr) {
    asm volatile("ldmatrix.sync.aligned.m8n8.x4.trans.shared.b16 {%0,%1,%2,%3}, [%4];"
                 : "=r"(r[0]), "=r"(r[1]), "=r"(r[2]), "=r"(r[3]) : "r"(addr));
}
// fp32-accumulate fp16 mma (node kernel)
__device__ __forceinline__ void mma16816h(float* d, const uint32_t* a, uint32_t b0, uint32_t b1) {
    asm volatile("mma.sync.aligned.m16n8k16.row.col.f32.f16.f16.f32 "
                 "{%0,%1,%2,%3}, {%4,%5,%6,%7}, {%8,%9}, {%0,%1,%2,%3};"
                 : "+f"(d[0]), "+f"(d[1]), "+f"(d[2]), "+f"(d[3])
                 : "r"(a[0]), "r"(a[1]), "r"(a[2]), "r"(a[3]), "r"(b0), "r"(b1));
}
// fp16-accumulate fp16 mma (edge kernel)
__device__ __forceinline__ void mma16816hh(uint32_t* d, const uint32_t* a, uint32_t b0, uint32_t b1) {
    asm volatile("mma.sync.aligned.m16n8k16.row.col.f16.f16.f16.f16 "
                 "{%0,%1}, {%2,%3,%4,%5}, {%6,%7}, {%0,%1};"
                 : "+r"(d[0]), "+r"(d[1])
                 : "r"(a[0]), "r"(a[1]), "r"(a[2]), "r"(a[3]), "r"(b0), "r"(b1));
}
__device__ __forceinline__ void cp_async16(uint32_t saddr, const void* g) {
    asm volatile("cp.async.cg.shared.global [%0], [%1], 16;" :: "r"(saddr), "l"(g));
}
#define CP_COMMIT() asm volatile("cp.async.commit_group;")
#define CP_WAIT0()  asm volatile("cp.async.wait_group 0;" ::: "memory")

__device__ __forceinline__ uint32_t pack_h(float v0, float v1) {
    return (uint32_t)__half_as_ushort(__float2half_rn(v0)) |
           ((uint32_t)__half_as_ushort(__float2half_rn(v1)) << 16);
}
__device__ __forceinline__ void split_pack_h(float v0, float v1, uint32_t& hi, uint32_t& lo) {
    __half h0 = __float2half_rn(v0), h1 = __float2half_rn(v1);
    hi = (uint32_t)__half_as_ushort(h0) | ((uint32_t)__half_as_ushort(h1) << 16);
    float r0 = v0 - __half2float(h0), r1 = v1 - __half2float(h1);
    lo = (uint32_t)__half_as_ushort(__float2half_rn(r0)) |
         ((uint32_t)__half_as_ushort(__float2half_rn(r1)) << 16);
}
__device__ __forceinline__ float2 unpack_h2sum(uint32_t hi, uint32_t lo) {
    float2 r;
    r.x = __half2float(__ushort_as_half((unsigned short)(hi & 0xffff))) +
          __half2float(__ushort_as_half((unsigned short)(lo & 0xffff)));
    r.y = __half2float(__ushort_as_half((unsigned short)(hi >> 16))) +
          __half2float(__ushort_as_half((unsigned short)(lo >> 16)));
    return r;
}

// edge k16 step: fp16-acc, single-term, 16 mma
#define KSTEP_E1H(HACC, fAh, sBhi, brow) do { \
    _Pragma("unroll") for (int p = 0; p < 8; p++) { \
        uint32_t bh[4]; \
        uint32_t _bo = b_frag_off + (brow) + (uint32_t)(p * 16) * 2; \
        ldsm_x4_t(bh, (sBhi) + _bo); \
        mma16816hh((HACC)[2 * p],     fAh, bh[0], bh[1]); \
        mma16816hh((HACC)[2 * p + 1], fAh, bh[2], bh[3]); \
    } } while (0)

// node single-term fp16 k16 step, fp32 acc, 16 mma
#define KSTEP_N1(ACC, fAh, sBhi, brow) do { \
    _Pragma("unroll") for (int p = 0; p < 8; p++) { \
        uint32_t bh[4]; \
        uint32_t _bo = b_frag_off + (brow) + (uint32_t)(p * 16) * 2; \
        ldsm_x4_t(bh, (sBhi) + _bo); \
        mma16816h((ACC)[2 * p],     fAh, bh[0], bh[1]); \
        mma16816h((ACC)[2 * p + 1], fAh, bh[2], bh[3]); \
    } } while (0)

// ---------------------------------------------------------------------------
// Weight prep (+ index dtype detection folded in): all weights -> fp16
// ---------------------------------------------------------------------------
__global__ void prep_weights_kernel(const float* __restrict__ W1,
                                    const float* __restrict__ W2,
                                    const float* __restrict__ W3,
                                    const float* __restrict__ D1,
                                    const float* __restrict__ D2,
                                    const void* __restrict__ eidx) {
    int idx = blockIdx.x * 256 + threadIdx.x;    // 0 .. 196607
    if (idx == 0) {
        const long long* p = (const long long*)eidx;
        int is64 = 1;
        for (int i = 0; i < 64; i++) {
            long long v = p[i];
            if (v < 0 || v >= N_NODES) { is64 = 0; break; }
        }
        g_idx_is64 = is64;
    }
    if (idx < 65536) {
        int n = idx & 127;
        int krow = idx >> 7;
        const float* W; int k, unit;
        if (krow < 256)      { W = W1; k = krow;       unit = krow >> 6; }
        else if (krow < 384) { W = W2; k = krow - 256; unit = 4 + ((krow - 256) >> 6); }
        else                 { W = W3; k = krow - 384; unit = 6 + ((krow - 384) >> 6); }
        float v = W[(size_t)k * 128 + n];
        int kk = k & 63;
        *(unsigned short*)(g_Bh16 + (size_t)unit * ECHUNK + (size_t)(kk * SB_STRIDE + n) * 2) =
            __half_as_ushort(__float2half_rn(v));
        return;
    }
    float v; int unit, kk, n;
    if (idx < 131072) {
        int i = idx - 65536;                     // D1: 128 x 512
        int k = i >> 9, n512 = i & 511;
        int c = n512 >> 7; n = n512 & 127;
        int half = k >> 6; kk = k & 63;
        unit = 4 * c + half;
        v = D1[(size_t)k * 512 + n512];
    } else {
        int i = idx - 131072;                    // D2: 512 x 128
        int k = i >> 7; n = i & 127;
        int c = k >> 7, krem = k & 127;
        int half = krem >> 6; kk = krem & 63;
        unit = 4 * c + 2 + half;
        v = D2[(size_t)k * 128 + n];
    }
    *(unsigned short*)(g_Bn16 + (size_t)unit * ECHUNK + (size_t)(kk * SB_STRIDE + n) * 2) =
        __half_as_ushort(__float2half_rn(v));
}

// ===========================================================================
// Edge kernel: fp16-acc HMMA 3-layer MLP; WARP-LOCAL restage + scatter
// ===========================================================================
__global__ __launch_bounds__(256, 2)
void edge_mma_kernel(const float* __restrict__ hE, const void* __restrict__ eidx,
                     const float* __restrict__ b1, const float* __restrict__ b2,
                     const float* __restrict__ b3) {
    extern __shared__ char sm[];
    const uint32_t sb = smem_u32(sm);
    const int tid = threadIdx.x, wid = tid >> 5, lane = tid & 31;
    const long long ebase = (long long)blockIdx.x * M_TILE;

    if (tid < 128) {
        ((float*)sm)[tid] = b1[tid];
        ((float*)sm)[128 + tid] = b2[tid];
        ((float*)sm)[256 + tid] = b3[tid];
    }

    for (int i = tid; i < 1088; i += 256)
        cp_async16(sb + OFF_SB + i * 16, g_Bh16 + i * 16);
    CP_COMMIT();

    {
        const float4* gE = (const float4*)(hE + ebase * HE);
        char* aHi = sm + OFF_AHI;
        for (int i = tid; i < 128 * 64; i += 256) {
            int row = i >> 6, c4 = i & 63;
            float4 v = gE[i];
            uint32_t off = (uint32_t)(row * SA_STRIDE + c4 * 4) * 2;
            *(uint2*)(aHi + off) = make_uint2(pack_h(v.x, v.y), pack_h(v.z, v.w));
        }
    }
    CP_WAIT0();
    __syncthreads();

    const int mrow = lane & 7, mid = lane >> 3;
    const uint32_t a_row_off =
        (uint32_t)((wid * 16 + (mid & 1) * 8 + mrow) * SA_STRIDE + (mid >> 1) * 8) * 2;
    const uint32_t b_frag_off =
        (uint32_t)(((mid & 1) * 8 + mrow) * SB_STRIDE + (mid >> 1) * 8) * 2;
    const int bq = 2 * (lane & 3);

    uint32_t hacc[16][2];
    uint32_t aH[8][4];
    float* sBias = (float*)sm;

#define ZERO_ACC() do { \
    _Pragma("unroll") for (int t = 0; t < 16; t++) { hacc[t][0] = 0u; hacc[t][1] = 0u; } } while (0)

#define PREFETCH(c) do { \
    const unsigned char* _src = g_Bh16 + (c) * ECHUNK; \
    uint32_t _dst = sb + OFF_SB + ((c) & 1) * ECHUNK; \
    for (int i = tid; i < 1088; i += 256) cp_async16(_dst + i * 16, _src + i * 16); \
    CP_COMMIT(); } while (0)

#define COMPUTE_SMEM(c) do { \
    uint32_t _sBhi = sb + OFF_SB + ((c) & 1) * ECHUNK; \
    _Pragma("unroll") for (int js = 0; js < 4; js++) { \
        uint32_t fAh[4]; \
        uint32_t _acol = (uint32_t)((c) * 64 + js * 16) * 2; \
        ldsm_x4(fAh, sb + OFF_AHI + a_row_off + _acol); \
        KSTEP_E1H(hacc, fAh, _sBhi, (uint32_t)(js * 16 * SB_STRIDE) * 2); \
    } } while (0)

#define COMPUTE_REG(JB, c) do { \
    uint32_t _sBhi = sb + OFF_SB + ((c) & 1) * ECHUNK; \
    _Pragma("unroll") for (int js = 0; js < 4; js++) { \
        KSTEP_E1H(hacc, aH[(JB) + js], _sBhi, (uint32_t)(js * 16 * SB_STRIDE) * 2); \
    } } while (0)

#define EPILOGUE_RELU(biasBase) do { \
    __half2 _z = __float2half2_rn(0.f); \
    _Pragma("unroll") for (int t = 0; t < 16; t++) { \
        float2 bb = *(float2*)&sBias[(biasBase) + t * 8 + bq]; \
        __half2 hb = __floats2half2_rn(bb.x, bb.y); \
        __half2 v01 = __hmax2(__hadd2(*(__half2*)&hacc[t][0], hb), _z); \
        __half2 v23 = __hmax2(__hadd2(*(__half2*)&hacc[t][1], hb), _z); \
        int _j = t >> 1, _b = (t & 1) * 2; \
        aH[_j][_b]     = *(uint32_t*)&v01; \
        aH[_j][_b + 1] = *(uint32_t*)&v23; \
    } } while (0)

    ZERO_ACC();
    PREFETCH(1); COMPUTE_SMEM(0); CP_WAIT0(); __syncthreads();
    PREFETCH(2); COMPUTE_SMEM(1); CP_WAIT0(); __syncthreads();
    PREFETCH(3); COMPUTE_SMEM(2); CP_WAIT0(); __syncthreads();
    PREFETCH(4); COMPUTE_SMEM(3); CP_WAIT0(); __syncthreads();
    EPILOGUE_RELU(0); ZERO_ACC();
    PREFETCH(5); COMPUTE_REG(0, 4); CP_WAIT0(); __syncthreads();
    PREFETCH(6); COMPUTE_REG(4, 5); CP_WAIT0(); __syncthreads();
    EPILOGUE_RELU(128); ZERO_ACC();
    PREFETCH(7); COMPUTE_REG(0, 6); CP_WAIT0(); __syncthreads();
    COMPUTE_REG(4, 7);
    // NOTE: no __syncthreads here. Layers 2/3 read only registers + B smem;
    // the A region (reused below as sOut) was last read in layer-1, which is
    // barrier-separated. Each warp restages and scatters ONLY its own 16 rows,
    // so the epilogue/scatter is fully warp-local.
    {
        float* sOut = (float*)(sm + OFF_AHI);   // 128 x 132 f32, warp-sliced
        int row0 = wid * 16 + (lane >> 2);
#pragma unroll
        for (int t = 0; t < 16; t++) {
            float2 bb = *(float2*)&sBias[256 + t * 8 + bq];
            __half2 v01 = *(__half2*)&hacc[t][0];
            __half2 v23 = *(__half2*)&hacc[t][1];
            *(float2*)&sOut[row0 * 132 + t * 8 + bq] =
                make_float2(__low2float(v01) + bb.x, __high2float(v01) + bb.y);
            *(float2*)&sOut[(row0 + 8) * 132 + t * 8 + bq] =
                make_float2(__low2float(v23) + bb.x, __high2float(v23) + bb.y);
        }
        __syncwarp();

        const int is64 = g_idx_is64;
        const int e0 = wid * 16;
#pragma unroll 1
        for (int e = e0; e < e0 + 16; e++) {
            long long s = is64 ? ((const long long*)eidx)[ebase + e]
                               : (long long)((const int*)eidx)[ebase + e];
            float* dst = g_dh + (size_t)s * H;
            const float* srow = sOut + e * 132;
#pragma unroll
            for (int q = 0; q < 4; q++) {
                int col = lane + q * 32;
                atomicAdd(dst + col, srow[col]);
            }
        }
    }
#undef ZERO_ACC
#undef PREFETCH
#undef COMPUTE_SMEM
#undef COMPUTE_REG
#undef EPILOGUE_RELU
}

// ===========================================================================
// Node kernel: single-term fp16 HMMA FFN, 64 rows / 128 threads / 2 CTAs/SM
// (unchanged from R16)
// ===========================================================================
__global__ __launch_bounds__(128, 2)
void node_mma_kernel(const float* __restrict__ hV,
                     const float* __restrict__ db1, const float* __restrict__ db2,
                     const float* __restrict__ g1, const float* __restrict__ be1,
                     const float* __restrict__ g2, const float* __restrict__ be2,
                     float* __restrict__ out) {
    extern __shared__ char sm[];
    const uint32_t sb = smem_u32(sm);
    const int tid = threadIdx.x, wid = tid >> 5, lane = tid & 31;
    const long long nbase = (long long)blockIdx.x * 64;

    float* sB = (float*)sm;
    for (int i = tid; i < 512; i += 128) sB[i] = db1[i];
    if (tid < 128) {
        sB[512 + tid] = db2[tid];
        sB[640 + tid] = g1[tid];  sB[768 + tid] = be1[tid];
        sB[896 + tid] = g2[tid];  sB[1024 + tid] = be2[tid];
    }

#define PREFETCH_N(s) do { \
    const unsigned char* _src = g_Bn16 + (s) * ECHUNK; \
    uint32_t _dst = sb + NOFF_NB + ((s) & 1) * ECHUNK; \
    for (int i = tid; i < 1088; i += 128) cp_async16(_dst + i * 16, _src + i * 16); \
    CP_COMMIT(); } while (0)

    PREFETCH_N(0);

    const int mrow = lane & 7, mid = lane >> 3;
    const uint32_t a_row_off =
        (uint32_t)((wid * 16 + (mid & 1) * 8 + mrow) * SB_STRIDE + (mid >> 1) * 8) * 2;
    const uint32_t b_frag_off =
        (uint32_t)(((mid & 1) * 8 + mrow) * SB_STRIDE + (mid >> 1) * 8) * 2;
    const int bq = 2 * (lane & 3);
    const int r0 = wid * 16 + (lane >> 2);      // 0..63
    const long long gr0 = nbase + r0, gr1 = gr0 + 8;
    const bool ok0 = gr0 < N_NODES, ok1 = gr1 < N_NODES;

    // ---- x = hV + dh/30 in fragment layout; LN1 in regs; A1 = fp16 hi(+lo smem) ----
    {
        float x[16][4];
#pragma unroll
        for (int t = 0; t < 16; t++) {
            int col = t * 8 + bq;
            if (ok0) {
                float2 v = *(const float2*)(hV + gr0 * H + col);
                float2 d = *(const float2*)(g_dh + gr0 * H + col);
                x[t][0] = v.x + d.x * (1.f / 30.f);
                x[t][1] = v.y + d.y * (1.f / 30.f);
            } else { x[t][0] = 0.f; x[t][1] = 0.f; }
            if (ok1) {
                float2 v = *(const float2*)(hV + gr1 * H + col);
                float2 d = *(const float2*)(g_dh + gr1 * H + col);
                x[t][2] = v.x + d.x * (1.f / 30.f);
                x[t][3] = v.y + d.y * (1.f / 30.f);
            } else { x[t][2] = 0.f; x[t][3] = 0.f; }
        }
        float s0 = 0.f, s1 = 0.f;
#pragma unroll
        for (int t = 0; t < 16; t++) { s0 += x[t][0] + x[t][1]; s1 += x[t][2] + x[t][3]; }
        s0 += __shfl_xor_sync(~0u, s0, 1); s0 += __shfl_xor_sync(~0u, s0, 2);
        s1 += __shfl_xor_sync(~0u, s1, 1); s1 += __shfl_xor_sync(~0u, s1, 2);
        float m0 = s0 * (1.f / H), m1 = s1 * (1.f / H);
        float q0 = 0.f, q1 = 0.f;
#pragma unroll
        for (int t = 0; t < 16; t++) {
            float d0 = x[t][0] - m0, d1 = x[t][1] - m0;
            float d2 = x[t][2] - m1, d3 = x[t][3] - m1;
            q0 += d0 * d0 + d1 * d1; q1 += d2 * d2 + d3 * d3;
        }
        q0 += __shfl_xor_sync(~0u, q0, 1); q0 += __shfl_xor_sync(~0u, q0, 2);
        q1 += __shfl_xor_sync(~0u, q1, 1); q1 += __shfl_xor_sync(~0u, q1, 2);
        float r0s = rsqrtf(q0 * (1.f / H) + EPS), r1s = rsqrtf(q1 * (1.f / H) + EPS);
#pragma unroll
        for (int t = 0; t < 16; t++) {
            int col = t * 8 + bq;
            float2 gg = *(float2*)&sB[640 + col];
            float2 bb = *(float2*)&sB[768 + col];
            float h0 = (x[t][0] - m0) * r0s * gg.x + bb.x;
            float h1 = (x[t][1] - m0) * r0s * gg.y + bb.y;
            float h2 = (x[t][2] - m1) * r1s * gg.x + bb.x;
            float h3 = (x[t][3] - m1) * r1s * gg.y + bb.y;
            uint32_t hi0, lo0, hi1, lo1;
            split_pack_h(h0, h1, hi0, lo0);
            split_pack_h(h2, h3, hi1, lo1);
            uint32_t o0 = (uint32_t)(r0 * SB_STRIDE + col) * 2;
            uint32_t o1 = (uint32_t)((r0 + 8) * SB_STRIDE + col) * 2;
            *(uint32_t*)(sm + NOFF_A1HI + o0) = hi0;
            *(uint32_t*)(sm + NOFF_A1LO + o0) = lo0;
            *(uint32_t*)(sm + NOFF_A1HI + o1) = hi1;
            *(uint32_t*)(sm + NOFF_A1LO + o1) = lo1;
        }
    }
    CP_WAIT0();
    __syncthreads();

    float acc2[16][4];
#pragma unroll
    for (int t = 0; t < 16; t++)
        { acc2[t][0] = 0.f; acc2[t][1] = 0.f; acc2[t][2] = 0.f; acc2[t][3] = 0.f; }

#define NCOMPUTE1(half, s) do { \
    uint32_t _sBhi = sb + NOFF_NB + ((s) & 1) * ECHUNK; \
    _Pragma("unroll") for (int js = 0; js < 4; js++) { \
        uint32_t fAh[4]; \
        uint32_t _acol = (uint32_t)((half) * 64 + js * 16) * 2; \
        ldsm_x4(fAh, sb + NOFF_A1HI + a_row_off + _acol); \
        KSTEP_N1(acc1, fAh, _sBhi, (uint32_t)(js * 16 * SB_STRIDE) * 2); \
    } } while (0)

#define NCOMPUTE2(half, s) do { \
    uint32_t _sBhi = sb + NOFF_NB + ((s) & 1) * ECHUNK; \
    _Pragma("unroll") for (int js = 0; js < 4; js++) { \
        uint32_t fAh[4]; \
        uint32_t _acol = (uint32_t)((half) * 64 + js * 16) * 2; \
        ldsm_x4(fAh, sb + NOFF_A2 + a_row_off + _acol); \
        KSTEP_N1(acc2, fAh, _sBhi, (uint32_t)(js * 16 * SB_STRIDE) * 2); \
    } } while (0)

#pragma unroll 1
    for (int c = 0; c < 4; c++) {
        const int s0u = 4 * c;
        float acc1[16][4];
#pragma unroll
        for (int t = 0; t < 16; t++)
            { acc1[t][0] = 0.f; acc1[t][1] = 0.f; acc1[t][2] = 0.f; acc1[t][3] = 0.f; }

        PREFETCH_N(s0u + 1); NCOMPUTE1(0, s0u);     CP_WAIT0(); __syncthreads();
        PREFETCH_N(s0u + 2); NCOMPUTE1(1, s0u + 1); CP_WAIT0(); __syncthreads();

        // bias + relu -> packed fp16 into A2 smem (own rows only)
#pragma unroll
        for (int t = 0; t < 16; t++) {
            float2 bb = *(float2*)&sB[c * 128 + t * 8 + bq];
            float v0 = fmaxf(acc1[t][0] + bb.x, 0.f);
            float v1 = fmaxf(acc1[t][1] + bb.y, 0.f);
            float v2 = fmaxf(acc1[t][2] + bb.x, 0.f);
            float v3 = fmaxf(acc1[t][3] + bb.y, 0.f);
            int col = t * 8 + bq;
            uint32_t o0 = (uint32_t)(r0 * SB_STRIDE + col) * 2;
            uint32_t o1 = (uint32_t)((r0 + 8) * SB_STRIDE + col) * 2;
            *(uint32_t*)(sm + NOFF_A2 + o0) = pack_h(v0, v1);
            *(uint32_t*)(sm + NOFF_A2 + o1) = pack_h(v2, v3);
        }
        __syncwarp();   // each warp's ldsm reads only rows it wrote

        PREFETCH_N(s0u + 3); NCOMPUTE2(0, s0u + 2); CP_WAIT0(); __syncthreads();
        if (c < 3) {
            PREFETCH_N(s0u + 4); NCOMPUTE2(1, s0u + 3); CP_WAIT0(); __syncthreads();
        } else {
            NCOMPUTE2(1, s0u + 3); __syncthreads();
        }
    }

    // ---- residual + LN2 + store ----
    {
        float y[16][4];
#pragma unroll
        for (int t = 0; t < 16; t++) {
            int col = t * 8 + bq;
            float2 d2 = *(float2*)&sB[512 + col];
            uint32_t o0 = (uint32_t)(r0 * SB_STRIDE + col) * 2;
            uint32_t o1 = (uint32_t)((r0 + 8) * SB_STRIDE + col) * 2;
            float2 h01 = unpack_h2sum(*(uint32_t*)(sm + NOFF_A1HI + o0),
                                      *(uint32_t*)(sm + NOFF_A1LO + o0));
            float2 h23 = unpack_h2sum(*(uint32_t*)(sm + NOFF_A1HI + o1),
                                      *(uint32_t*)(sm + NOFF_A1LO + o1));
            y[t][0] = h01.x + acc2[t][0] + d2.x;
            y[t][1] = h01.y + acc2[t][1] + d2.y;
            y[t][2] = h23.x + acc2[t][2] + d2.x;
            y[t][3] = h23.y + acc2[t][3] + d2.y;
        }
        float s0 = 0.f, s1 = 0.f;
#pragma unroll
        for (int t = 0; t < 16; t++) { s0 += y[t][0] + y[t][1]; s1 += y[t][2] + y[t][3]; }
        s0 += __shfl_xor_sync(~0u, s0, 1); s0 += __shfl_xor_sync(~0u, s0, 2);
        s1 += __shfl_xor_sync(~0u, s1, 1); s1 += __shfl_xor_sync(~0u, s1, 2);
        float m0 = s0 * (1.f / H), m1 = s1 * (1.f / H);
        float q0 = 0.f, q1 = 0.f;
#pragma unroll
        for (int t = 0; t < 16; t++) {
            float d0 = y[t][0] - m0, d1 = y[t][1] - m0;
            float d2 = y[t][2] - m1, d3 = y[t][3] - m1;
            q0 += d0 * d0 + d1 * d1; q1 += d2 * d2 + d3 * d3;
        }
        q0 += __shfl_xor_sync(~0u, q0, 1); q0 += __shfl_xor_sync(~0u, q0, 2);
        q1 += __shfl_xor_sync(~0u, q1, 1); q1 += __shfl_xor_sync(~0u, q1, 2);
        float r0s = rsqrtf(q0 * (1.f / H) + EPS), r1s = rsqrtf(q1 * (1.f / H) + EPS);
#pragma unroll
        for (int t = 0; t < 16; t++) {
            int col = t * 8 + bq;
            float2 gg = *(float2*)&sB[896 + col];
            float2 bb = *(float2*)&sB[1024 + col];
            if (ok0) {
                float2 o;
                o.x = (y[t][0] - m0) * r0s * gg.x + bb.x;
                o.y = (y[t][1] - m0) * r0s * gg.y + bb.y;
                *(float2*)(out + gr0 * H + col) = o;
            }
            if (ok1) {
                float2 o;
                o.x = (y[t][2] - m1) * r1s * gg.x + bb.x;
                o.y = (y[t][3] - m1) * r1s * gg.y + bb.y;
                *(float2*)(out + gr1 * H + col) = o;
            }
        }
    }
#undef PREFETCH_N
#undef NCOMPUTE1
#undef NCOMPUTE2
}

// ===========================================================================
extern "C" void kernel_launch(void* const* d_in, const int* in_sizes, int n_in,
                              void* d_out, int out_size) {
    const float* h_V  = (const float*)d_in[0];
    const float* h_E  = (const float*)d_in[1];
    const void*  eidx = (const void*)d_in[2];
    const float* W1 = (const float*)d_in[3];
    const float* b1 = (const float*)d_in[4];
    const float* W2 = (const float*)d_in[5];
    const float* b2 = (const float*)d_in[6];
    const float* W3 = (const float*)d_in[7];
    const float* b3 = (const float*)d_in[8];
    const float* D1 = (const float*)d_in[9];
    const float* db1 = (const float*)d_in[10];
    const float* D2 = (const float*)d_in[11];
    const float* db2 = (const float*)d_in[12];
    const float* g1 = (const float*)d_in[13];
    const float* be1 = (const float*)d_in[14];
    const float* g2 = (const float*)d_in[15];
    const float* be2 = (const float*)d_in[16];
    float* out = (float*)d_out;

    cudaFuncSetAttribute(edge_mma_kernel, cudaFuncAttributeMaxDynamicSharedMemorySize, EDGE_SMEM);
    cudaFuncSetAttribute(node_mma_kernel, cudaFuncAttributeMaxDynamicSharedMemorySize, NODE_SMEM);

    void* dh_ptr = nullptr;
    cudaGetSymbolAddress(&dh_ptr, g_dh);
    cudaMemsetAsync(dh_ptr, 0, sizeof(float) * (size_t)N_NODES * H, 0);

    prep_weights_kernel<<<768, 256>>>(W1, W2, W3, D1, D2, eidx);
    edge_mma_kernel<<<N_EDGES / M_TILE, 256, EDGE_SMEM>>>(h_E, eidx, b1, b2, b3);
    node_mma_kernel<<<(N_NODES + 63) / 64, 128, NODE_SMEM>>>(
        h_V, db1, db2, g1, be1, g2, be2, out);
}